// round 1
// baseline (speedup 1.0000x reference)
#include <cuda_runtime.h>
#include <stdint.h>

#define B_   8
#define N_   1024
#define C_   1024
#define H_   16
#define HD_  64
#define FF_  4096
#define BH_  (B_*H_)      /* 128 */
#define M_   (B_*N_)      /* 8192 */
#define KSP  102          /* int(0.1*1024) */

// ---------------- scratch (device globals; no allocations allowed) ----------
__device__ float g_xn[M_*C_];                 // LN1 output
__device__ float g_q[BH_*N_*HD_];             // [bh][n][d]
__device__ float g_k[BH_*N_*HD_];
__device__ float g_v[BH_*N_*HD_];
__device__ float g_attn[M_*C_];               // attention output [b*1024+n][h*64+d]
__device__ float g_x1[M_*C_];                 // after attention residual
__device__ float g_hn[M_*C_];                 // LN2 output
__device__ float g_h1[(size_t)M_*FF_];        // FFN intermediate

// ---------------- LayerNorm ---------------------------------------------
__global__ void __launch_bounds__(256)
ln_kernel(const float* __restrict__ x, const float* __restrict__ w,
          const float* __restrict__ b, float* __restrict__ y)
{
    __shared__ float red[16];
    int row = blockIdx.x;
    const float4* xr = (const float4*)(x + (size_t)row * 1024);
    int t = threadIdx.x;
    float4 v = xr[t];
    float s  = v.x + v.y + v.z + v.w;
    float ss = v.x*v.x + v.y*v.y + v.z*v.z + v.w*v.w;
    #pragma unroll
    for (int o = 16; o; o >>= 1) {
        s  += __shfl_xor_sync(0xFFFFFFFFu, s, o);
        ss += __shfl_xor_sync(0xFFFFFFFFu, ss, o);
    }
    int lane = t & 31, wid = t >> 5;
    if (lane == 0) { red[wid] = s; red[wid + 8] = ss; }
    __syncthreads();
    if (t == 0) {
        float ts = 0.f, tss = 0.f;
        #pragma unroll
        for (int i = 0; i < 8; ++i) { ts += red[i]; tss += red[i + 8]; }
        float mu  = ts * (1.f / 1024.f);
        float var = tss * (1.f / 1024.f) - mu * mu;
        red[0] = mu;
        red[1] = rsqrtf(var + 1e-5f);
    }
    __syncthreads();
    float mu = red[0], rs = red[1];
    float4 wv = ((const float4*)w)[t];
    float4 bv = ((const float4*)b)[t];
    float4 o;
    o.x = (v.x - mu) * rs * wv.x + bv.x;
    o.y = (v.y - mu) * rs * wv.y + bv.y;
    o.z = (v.z - mu) * rs * wv.z + bv.z;
    o.w = (v.w - mu) * rs * wv.w + bv.w;
    ((float4*)(y + (size_t)row * 1024))[t] = o;
}

// ---------------- GEMM: C = A @ B^T (+epilogue) --------------------------
// A: [M,K] row-major, B: [N,K] row-major. 128x128x16 tile, 8x8 per thread.
// EPI 0: QKV scatter (+qkv_b)     -> g_q/g_k/g_v
// EPI 1: out = acc + bias + res
// EPI 2: out = relu((acc+bias)) * (aux>0.5)
// EPI 3: out = res + (acc+bias)*(aux>0.5)
template<int EPI>
__global__ void __launch_bounds__(256)
gemm_nt(const float* __restrict__ A, const float* __restrict__ Bm,
        const float* __restrict__ bias, const float* __restrict__ aux,
        const float* __restrict__ res, float* __restrict__ out,
        int M, int N, int K)
{
    __shared__ float As[2][16][128];
    __shared__ float Bs[2][16][128];
    const int tid = threadIdx.x;
    const int tx = tid & 15;
    const int ty = tid >> 4;
    const int bm = blockIdx.y * 128;
    const int bn = blockIdx.x * 128;

    const int lr = tid >> 2;          // 0..63
    const int lc = (tid & 3) << 2;    // 0,4,8,12

    const float* Ap = A  + (size_t)(bm + lr) * K + lc;
    const float* Bp = Bm + (size_t)(bn + lr) * K + lc;
    const size_t strd = (size_t)64 * K;

    float acc[8][8];
    #pragma unroll
    for (int i = 0; i < 8; ++i)
        #pragma unroll
        for (int j = 0; j < 8; ++j) acc[i][j] = 0.f;

    float4 a0 = *(const float4*)Ap;
    float4 a1 = *(const float4*)(Ap + strd);
    float4 b0 = *(const float4*)Bp;
    float4 b1 = *(const float4*)(Bp + strd);

    int buf = 0;
    const int ktn = K >> 4;
    for (int kt = 0; kt < ktn; ++kt) {
        As[buf][lc+0][lr]    = a0.x; As[buf][lc+1][lr]    = a0.y;
        As[buf][lc+2][lr]    = a0.z; As[buf][lc+3][lr]    = a0.w;
        As[buf][lc+0][lr+64] = a1.x; As[buf][lc+1][lr+64] = a1.y;
        As[buf][lc+2][lr+64] = a1.z; As[buf][lc+3][lr+64] = a1.w;
        Bs[buf][lc+0][lr]    = b0.x; Bs[buf][lc+1][lr]    = b0.y;
        Bs[buf][lc+2][lr]    = b0.z; Bs[buf][lc+3][lr]    = b0.w;
        Bs[buf][lc+0][lr+64] = b1.x; Bs[buf][lc+1][lr+64] = b1.y;
        Bs[buf][lc+2][lr+64] = b1.z; Bs[buf][lc+3][lr+64] = b1.w;
        __syncthreads();
        if (kt + 1 < ktn) {
            const float* Ap2 = Ap + (size_t)(kt + 1) * 16;
            const float* Bp2 = Bp + (size_t)(kt + 1) * 16;
            a0 = *(const float4*)Ap2;
            a1 = *(const float4*)(Ap2 + strd);
            b0 = *(const float4*)Bp2;
            b1 = *(const float4*)(Bp2 + strd);
        }
        #pragma unroll
        for (int kk = 0; kk < 16; ++kk) {
            float af[8], bf[8];
            *(float4*)&af[0] = *(const float4*)&As[buf][kk][ty*8];
            *(float4*)&af[4] = *(const float4*)&As[buf][kk][ty*8 + 4];
            *(float4*)&bf[0] = *(const float4*)&Bs[buf][kk][tx*8];
            *(float4*)&bf[4] = *(const float4*)&Bs[buf][kk][tx*8 + 4];
            #pragma unroll
            for (int i = 0; i < 8; ++i)
                #pragma unroll
                for (int j = 0; j < 8; ++j)
                    acc[i][j] = fmaf(af[i], bf[j], acc[i][j]);
        }
        buf ^= 1;
    }

    #pragma unroll
    for (int i = 0; i < 8; ++i) {
        int gi = bm + ty*8 + i;
        #pragma unroll
        for (int j = 0; j < 8; ++j) {
            int gj = bn + tx*8 + j;
            float v = acc[i][j] + bias[gj];
            if (EPI == 0) {
                int which = gj >> 10;
                int h = (gj >> 6) & 15;
                int d = gj & 63;
                int bb = gi >> 10;
                int nn = gi & 1023;
                float* dst = (which == 0) ? g_q : ((which == 1) ? g_k : g_v);
                dst[(((size_t)(bb*16 + h)) * 1024 + nn) * 64 + d] = v;
            } else if (EPI == 1) {
                out[(size_t)gi * N + gj] = v + res[(size_t)gi * N + gj];
            } else if (EPI == 2) {
                out[(size_t)gi * N + gj] =
                    (aux[(size_t)gi * N + gj] > 0.5f) ? fmaxf(v, 0.f) : 0.f;
            } else {
                float m = (aux[(size_t)gi * N + gj] > 0.5f) ? 1.f : 0.f;
                out[(size_t)gi * N + gj] = res[(size_t)gi * N + gj] + v * m;
            }
        }
    }
}

// ---------------- Sparse attention --------------------------------------
// One block = (b,h) head + 16 query rows. 512 threads = 16 warps, warp w owns row w.
// smem: sQ[16*64] | sKV[128*68] | sS[16*1024]
#define ATTN_SMEM ((1024 + 128*68 + 16*1024) * 4)

__global__ void __launch_bounds__(512)
attn_kernel()
{
    extern __shared__ float sm[];
    float* sQ  = sm;                  // 1024
    float* sKV = sm + 1024;           // 8704
    float* sS  = sm + 1024 + 8704;    // 16384

    int blk = blockIdx.x;
    int bh  = blk >> 6;
    int n0  = (blk & 63) << 4;
    const float* Q  = g_q + (size_t)bh * (N_*HD_);
    const float* Kp = g_k + (size_t)bh * (N_*HD_);
    const float* Vp = g_v + (size_t)bh * (N_*HD_);

    int tid = threadIdx.x;
    int lane = tid & 31;
    int w = tid >> 5;

    if (tid < 256)
        ((float4*)sQ)[tid] = ((const float4*)(Q + (size_t)n0 * HD_))[tid];

    // ---- Phase 1: scores (QK^T * scale) into sS ----
    for (int kt = 0; kt < 8; ++kt) {
        __syncthreads();
        #pragma unroll
        for (int it = 0; it < 4; ++it) {
            int idx = tid + it * 512;     // 0..2047
            int key = idx >> 4;
            int c   = idx & 15;
            float4 kv = ((const float4*)(Kp + (size_t)(kt*128 + key) * 64))[c];
            *(float4*)&sKV[key*68 + c*4] = kv;
        }
        __syncthreads();
        float acc0 = 0.f, acc1 = 0.f, acc2 = 0.f, acc3 = 0.f;
        const float4* q4 = (const float4*)&sQ[w * 64];
        #pragma unroll
        for (int c = 0; c < 16; ++c) {
            float4 qv = q4[c];
            float4 k0 = *(const float4*)&sKV[(lane     )*68 + c*4];
            float4 k1 = *(const float4*)&sKV[(lane + 32)*68 + c*4];
            float4 k2 = *(const float4*)&sKV[(lane + 64)*68 + c*4];
            float4 k3 = *(const float4*)&sKV[(lane + 96)*68 + c*4];
            acc0 = fmaf(qv.x,k0.x,fmaf(qv.y,k0.y,fmaf(qv.z,k0.z,fmaf(qv.w,k0.w,acc0))));
            acc1 = fmaf(qv.x,k1.x,fmaf(qv.y,k1.y,fmaf(qv.z,k1.z,fmaf(qv.w,k1.w,acc1))));
            acc2 = fmaf(qv.x,k2.x,fmaf(qv.y,k2.y,fmaf(qv.z,k2.z,fmaf(qv.w,k2.w,acc2))));
            acc3 = fmaf(qv.x,k3.x,fmaf(qv.y,k3.y,fmaf(qv.z,k3.z,fmaf(qv.w,k3.w,acc3))));
        }
        float* srow = &sS[w*1024 + kt*128];
        srow[lane     ] = acc0 * 0.125f;
        srow[lane + 32] = acc1 * 0.125f;
        srow[lane + 64] = acc2 * 0.125f;
        srow[lane + 96] = acc3 * 0.125f;
    }

    // ---- top-k (k=102) exact threshold via binary search on ordered keys ----
    // warp-local: each warp operates only on its own row of sS (no sync needed)
    unsigned key[32];
    float lmax = -3.4e38f;
    float* srow = &sS[w * 1024];
    #pragma unroll
    for (int i = 0; i < 32; ++i) {
        float s = srow[lane + 32*i];
        lmax = fmaxf(lmax, s);
        unsigned ub = __float_as_uint(s);
        key[i] = ub ^ (((unsigned)((int)ub >> 31)) | 0x80000000u);
    }
    #pragma unroll
    for (int o = 16; o; o >>= 1) lmax = fmaxf(lmax, __shfl_xor_sync(0xFFFFFFFFu, lmax, o));

    unsigned lo = 0u, hi = 0xFFFFFFFFu;
    while (lo < hi) {
        unsigned mid = lo + (unsigned)(((unsigned long long)(hi - lo) + 1ull) >> 1);
        unsigned c = 0;
        #pragma unroll
        for (int i = 0; i < 32; ++i) c += (key[i] >= mid) ? 1u : 0u;
        c = __reduce_add_sync(0xFFFFFFFFu, c);
        if (c >= (unsigned)KSP) lo = mid; else hi = mid - 1u;
    }
    unsigned T = lo;

    // ---- softmax over selected (excluded get exactly 0, matching exp(-1e9)) ----
    float lsum = 0.f;
    #pragma unroll
    for (int i = 0; i < 32; ++i) {
        float e = 0.f;
        if (key[i] >= T) {
            unsigned ub = key[i];
            unsigned fb = ub ^ ((ub & 0x80000000u) ? 0x80000000u : 0xFFFFFFFFu);
            e = __expf(__uint_as_float(fb) - lmax);
        }
        lsum += e;
        srow[lane + 32*i] = e;
    }
    #pragma unroll
    for (int o = 16; o; o >>= 1) lsum += __shfl_xor_sync(0xFFFFFFFFu, lsum, o);
    float inv = 1.f / lsum;
    #pragma unroll
    for (int i = 0; i < 32; ++i) srow[lane + 32*i] *= inv;

    // ---- Phase 2: out = P @ V (warp-uniform skip of zero probabilities) ----
    float o0 = 0.f, o1 = 0.f;
    for (int kt = 0; kt < 8; ++kt) {
        __syncthreads();
        #pragma unroll
        for (int it = 0; it < 4; ++it) {
            int idx = tid + it * 512;
            int keyi = idx >> 4;
            int c    = idx & 15;
            float4 vv = ((const float4*)(Vp + (size_t)(kt*128 + keyi) * 64))[c];
            *(float4*)&sKV[keyi*68 + c*4] = vv;
        }
        __syncthreads();
        const float* pr = &sS[w*1024 + kt*128];
        #pragma unroll 4
        for (int m = 0; m < 128; ++m) {
            float p = pr[m];                 // broadcast -> warp-uniform branch
            if (p != 0.f) {
                o0 = fmaf(p, sKV[m*68 + lane     ], o0);
                o1 = fmaf(p, sKV[m*68 + lane + 32], o1);
            }
        }
    }
    int bb = bh >> 4, hh = bh & 15;
    int nn = n0 + w;
    float* dst = g_attn + ((size_t)(bb*1024 + nn)) * 1024 + hh*64;
    dst[lane]      = o0;
    dst[lane + 32] = o1;
}

// ---------------- launch --------------------------------------------------
extern "C" void kernel_launch(void* const* d_in, const int* in_sizes, int n_in,
                              void* d_out, int out_size)
{
    (void)in_sizes; (void)n_in; (void)out_size;
    const float* x      = (const float*)d_in[0];
    const float* ln1_w  = (const float*)d_in[1];
    const float* ln1_b  = (const float*)d_in[2];
    const float* qkv_w  = (const float*)d_in[3];
    const float* qkv_b  = (const float*)d_in[4];
    const float* out_w  = (const float*)d_in[5];
    const float* out_b  = (const float*)d_in[6];
    const float* ln2_w  = (const float*)d_in[7];
    const float* ln2_b  = (const float*)d_in[8];
    const float* w1     = (const float*)d_in[9];
    const float* b1     = (const float*)d_in[10];
    const float* w2     = (const float*)d_in[11];
    const float* b2     = (const float*)d_in[12];
    const float* mask1  = (const float*)d_in[13];
    const float* mask2  = (const float*)d_in[14];
    float* out = (float*)d_out;

    float *p_xn, *p_attn, *p_x1, *p_hn, *p_h1;
    cudaGetSymbolAddress((void**)&p_xn,   g_xn);
    cudaGetSymbolAddress((void**)&p_attn, g_attn);
    cudaGetSymbolAddress((void**)&p_x1,   g_x1);
    cudaGetSymbolAddress((void**)&p_hn,   g_hn);
    cudaGetSymbolAddress((void**)&p_h1,   g_h1);

    cudaFuncSetAttribute(attn_kernel,
                         cudaFuncAttributeMaxDynamicSharedMemorySize, ATTN_SMEM);

    // 1) LN1
    ln_kernel<<<M_, 256>>>(x, ln1_w, ln1_b, p_xn);
    // 2) QKV projection (scatter into q/k/v)
    gemm_nt<0><<<dim3(3*C_/128, M_/128), 256>>>(p_xn, qkv_w, qkv_b,
                                                nullptr, nullptr, nullptr,
                                                M_, 3*C_, C_);
    // 3) sparse attention
    attn_kernel<<<BH_*(N_/16), 512, ATTN_SMEM>>>();
    // 4) output projection + residual
    gemm_nt<1><<<dim3(C_/128, M_/128), 256>>>(p_attn, out_w, out_b,
                                              nullptr, x, p_x1,
                                              M_, C_, C_);
    // 5) LN2
    ln_kernel<<<M_, 256>>>(p_x1, ln2_w, ln2_b, p_hn);
    // 6) FFN1: relu((hn @ w1^T + b1) * m1)
    gemm_nt<2><<<dim3(FF_/128, M_/128), 256>>>(p_hn, w1, b1,
                                               mask1, nullptr, p_h1,
                                               M_, FF_, C_);
    // 7) FFN2: x1 + (h1 @ w2^T + b2) * m2  -> d_out
    gemm_nt<3><<<dim3(C_/128, M_/128), 256>>>(p_h1, w2, b2,
                                              mask2, p_x1, out,
                                              M_, C_, FF_);
}

// round 2
// speedup vs baseline: 1.0026x; 1.0026x over previous
#include <cuda_runtime.h>
#include <stdint.h>

#define B_   8
#define N_   1024
#define C_   1024
#define H_   16
#define HD_  64
#define FF_  4096
#define BH_  (B_*H_)      /* 128 */
#define M_   (B_*N_)      /* 8192 */
#define KSP  102          /* int(0.1*1024) */

// ---------------- scratch (device globals; no allocations allowed) ----------
__device__ float g_xn[M_*C_];                 // LN1 output
__device__ float g_q[BH_*N_*HD_];             // [bh][n][d]
__device__ float g_k[BH_*N_*HD_];
__device__ float g_v[BH_*N_*HD_];
__device__ float g_attn[M_*C_];               // attention output [b*1024+n][h*64+d]
__device__ float g_x1[M_*C_];                 // after attention residual
__device__ float g_hn[M_*C_];                 // LN2 output
__device__ float g_h1[(size_t)M_*FF_];        // FFN intermediate

// ---------------- LayerNorm ---------------------------------------------
__global__ void __launch_bounds__(256)
ln_kernel(const float* __restrict__ x, const float* __restrict__ w,
          const float* __restrict__ b, float* __restrict__ y)
{
    __shared__ float red[16];
    int row = blockIdx.x;
    const float4* xr = (const float4*)(x + (size_t)row * 1024);
    int t = threadIdx.x;
    float4 v = xr[t];
    float s  = v.x + v.y + v.z + v.w;
    float ss = v.x*v.x + v.y*v.y + v.z*v.z + v.w*v.w;
    #pragma unroll
    for (int o = 16; o; o >>= 1) {
        s  += __shfl_xor_sync(0xFFFFFFFFu, s, o);
        ss += __shfl_xor_sync(0xFFFFFFFFu, ss, o);
    }
    int lane = t & 31, wid = t >> 5;
    if (lane == 0) { red[wid] = s; red[wid + 8] = ss; }
    __syncthreads();
    if (t == 0) {
        float ts = 0.f, tss = 0.f;
        #pragma unroll
        for (int i = 0; i < 8; ++i) { ts += red[i]; tss += red[i + 8]; }
        float mu  = ts * (1.f / 1024.f);
        float var = tss * (1.f / 1024.f) - mu * mu;
        red[0] = mu;
        red[1] = rsqrtf(var + 1e-5f);
    }
    __syncthreads();
    float mu = red[0], rs = red[1];
    float4 wv = ((const float4*)w)[t];
    float4 bv = ((const float4*)b)[t];
    float4 o;
    o.x = (v.x - mu) * rs * wv.x + bv.x;
    o.y = (v.y - mu) * rs * wv.y + bv.y;
    o.z = (v.z - mu) * rs * wv.z + bv.z;
    o.w = (v.w - mu) * rs * wv.w + bv.w;
    ((float4*)(y + (size_t)row * 1024))[t] = o;
}

// ---------------- GEMM: C = A @ B^T (+epilogue) --------------------------
// A: [M,K] row-major, B: [N,K] row-major. 128x128x16 tile, 8x8 per thread.
// EPI 0: QKV scatter (+qkv_b)     -> g_q/g_k/g_v
// EPI 1: out = acc + bias + res
// EPI 2: out = relu((acc+bias)) * (aux>0.5)
// EPI 3: out = res + (acc+bias)*(aux>0.5)
template<int EPI>
__global__ void __launch_bounds__(256)
gemm_nt(const float* __restrict__ A, const float* __restrict__ Bm,
        const float* __restrict__ bias, const float* __restrict__ aux,
        const float* __restrict__ res, float* __restrict__ out,
        int M, int N, int K)
{
    __shared__ float As[2][16][128];
    __shared__ float Bs[2][16][128];
    const int tid = threadIdx.x;
    const int tx = tid & 15;
    const int ty = tid >> 4;
    const int bm = blockIdx.y * 128;
    const int bn = blockIdx.x * 128;

    const int lr = tid >> 2;          // 0..63
    const int lc = (tid & 3) << 2;    // 0,4,8,12

    const float* Ap = A  + (size_t)(bm + lr) * K + lc;
    const float* Bp = Bm + (size_t)(bn + lr) * K + lc;
    const size_t strd = (size_t)64 * K;

    float acc[8][8];
    #pragma unroll
    for (int i = 0; i < 8; ++i)
        #pragma unroll
        for (int j = 0; j < 8; ++j) acc[i][j] = 0.f;

    float4 a0 = *(const float4*)Ap;
    float4 a1 = *(const float4*)(Ap + strd);
    float4 b0 = *(const float4*)Bp;
    float4 b1 = *(const float4*)(Bp + strd);

    int buf = 0;
    const int ktn = K >> 4;
    for (int kt = 0; kt < ktn; ++kt) {
        As[buf][lc+0][lr]    = a0.x; As[buf][lc+1][lr]    = a0.y;
        As[buf][lc+2][lr]    = a0.z; As[buf][lc+3][lr]    = a0.w;
        As[buf][lc+0][lr+64] = a1.x; As[buf][lc+1][lr+64] = a1.y;
        As[buf][lc+2][lr+64] = a1.z; As[buf][lc+3][lr+64] = a1.w;
        Bs[buf][lc+0][lr]    = b0.x; Bs[buf][lc+1][lr]    = b0.y;
        Bs[buf][lc+2][lr]    = b0.z; Bs[buf][lc+3][lr]    = b0.w;
        Bs[buf][lc+0][lr+64] = b1.x; Bs[buf][lc+1][lr+64] = b1.y;
        Bs[buf][lc+2][lr+64] = b1.z; Bs[buf][lc+3][lr+64] = b1.w;
        __syncthreads();
        if (kt + 1 < ktn) {
            const float* Ap2 = Ap + (size_t)(kt + 1) * 16;
            const float* Bp2 = Bp + (size_t)(kt + 1) * 16;
            a0 = *(const float4*)Ap2;
            a1 = *(const float4*)(Ap2 + strd);
            b0 = *(const float4*)Bp2;
            b1 = *(const float4*)(Bp2 + strd);
        }
        #pragma unroll
        for (int kk = 0; kk < 16; ++kk) {
            float af[8], bf[8];
            *(float4*)&af[0] = *(const float4*)&As[buf][kk][ty*8];
            *(float4*)&af[4] = *(const float4*)&As[buf][kk][ty*8 + 4];
            *(float4*)&bf[0] = *(const float4*)&Bs[buf][kk][tx*8];
            *(float4*)&bf[4] = *(const float4*)&Bs[buf][kk][tx*8 + 4];
            #pragma unroll
            for (int i = 0; i < 8; ++i)
                #pragma unroll
                for (int j = 0; j < 8; ++j)
                    acc[i][j] = fmaf(af[i], bf[j], acc[i][j]);
        }
        buf ^= 1;
    }

    #pragma unroll
    for (int i = 0; i < 8; ++i) {
        int gi = bm + ty*8 + i;
        #pragma unroll
        for (int j = 0; j < 8; ++j) {
            int gj = bn + tx*8 + j;
            float v = acc[i][j] + bias[gj];
            if (EPI == 0) {
                int which = gj >> 10;
                int h = (gj >> 6) & 15;
                int d = gj & 63;
                int bb = gi >> 10;
                int nn = gi & 1023;
                float* dst = (which == 0) ? g_q : ((which == 1) ? g_k : g_v);
                dst[(((size_t)(bb*16 + h)) * 1024 + nn) * 64 + d] = v;
            } else if (EPI == 1) {
                out[(size_t)gi * N + gj] = v + res[(size_t)gi * N + gj];
            } else if (EPI == 2) {
                out[(size_t)gi * N + gj] =
                    (aux[(size_t)gi * N + gj] > 0.5f) ? fmaxf(v, 0.f) : 0.f;
            } else {
                float m = (aux[(size_t)gi * N + gj] > 0.5f) ? 1.f : 0.f;
                out[(size_t)gi * N + gj] = res[(size_t)gi * N + gj] + v * m;
            }
        }
    }
}

// ---------------- Sparse attention --------------------------------------
// One block = (b,h) head + 16 query rows. 512 threads = 16 warps, warp w owns row w.
// smem: sQ[16*64] | sKV[128*68] | sS[16*1024]
#define ATTN_SMEM ((1024 + 128*68 + 16*1024) * 4)

__global__ void __launch_bounds__(512)
attn_kernel()
{
    extern __shared__ float sm[];
    float* sQ  = sm;                  // 1024
    float* sKV = sm + 1024;           // 8704
    float* sS  = sm + 1024 + 8704;    // 16384

    int blk = blockIdx.x;
    int bh  = blk >> 6;
    int n0  = (blk & 63) << 4;
    const float* Q  = g_q + (size_t)bh * (N_*HD_);
    const float* Kp = g_k + (size_t)bh * (N_*HD_);
    const float* Vp = g_v + (size_t)bh * (N_*HD_);

    int tid = threadIdx.x;
    int lane = tid & 31;
    int w = tid >> 5;

    if (tid < 256)
        ((float4*)sQ)[tid] = ((const float4*)(Q + (size_t)n0 * HD_))[tid];

    // ---- Phase 1: scores (QK^T * scale) into sS ----
    for (int kt = 0; kt < 8; ++kt) {
        __syncthreads();
        #pragma unroll
        for (int it = 0; it < 4; ++it) {
            int idx = tid + it * 512;     // 0..2047
            int key = idx >> 4;
            int c   = idx & 15;
            float4 kv = ((const float4*)(Kp + (size_t)(kt*128 + key) * 64))[c];
            *(float4*)&sKV[key*68 + c*4] = kv;
        }
        __syncthreads();
        float acc0 = 0.f, acc1 = 0.f, acc2 = 0.f, acc3 = 0.f;
        const float4* q4 = (const float4*)&sQ[w * 64];
        #pragma unroll
        for (int c = 0; c < 16; ++c) {
            float4 qv = q4[c];
            float4 k0 = *(const float4*)&sKV[(lane     )*68 + c*4];
            float4 k1 = *(const float4*)&sKV[(lane + 32)*68 + c*4];
            float4 k2 = *(const float4*)&sKV[(lane + 64)*68 + c*4];
            float4 k3 = *(const float4*)&sKV[(lane + 96)*68 + c*4];
            acc0 = fmaf(qv.x,k0.x,fmaf(qv.y,k0.y,fmaf(qv.z,k0.z,fmaf(qv.w,k0.w,acc0))));
            acc1 = fmaf(qv.x,k1.x,fmaf(qv.y,k1.y,fmaf(qv.z,k1.z,fmaf(qv.w,k1.w,acc1))));
            acc2 = fmaf(qv.x,k2.x,fmaf(qv.y,k2.y,fmaf(qv.z,k2.z,fmaf(qv.w,k2.w,acc2))));
            acc3 = fmaf(qv.x,k3.x,fmaf(qv.y,k3.y,fmaf(qv.z,k3.z,fmaf(qv.w,k3.w,acc3))));
        }
        float* srow = &sS[w*1024 + kt*128];
        srow[lane     ] = acc0 * 0.125f;
        srow[lane + 32] = acc1 * 0.125f;
        srow[lane + 64] = acc2 * 0.125f;
        srow[lane + 96] = acc3 * 0.125f;
    }

    // ---- top-k (k=102) exact threshold via binary search on ordered keys ----
    // warp-local: each warp operates only on its own row of sS (no sync needed)
    unsigned key[32];
    float lmax = -3.4e38f;
    float* srow = &sS[w * 1024];
    #pragma unroll
    for (int i = 0; i < 32; ++i) {
        float s = srow[lane + 32*i];
        lmax = fmaxf(lmax, s);
        unsigned ub = __float_as_uint(s);
        key[i] = ub ^ (((unsigned)((int)ub >> 31)) | 0x80000000u);
    }
    #pragma unroll
    for (int o = 16; o; o >>= 1) lmax = fmaxf(lmax, __shfl_xor_sync(0xFFFFFFFFu, lmax, o));

    unsigned lo = 0u, hi = 0xFFFFFFFFu;
    while (lo < hi) {
        unsigned mid = lo + (unsigned)(((unsigned long long)(hi - lo) + 1ull) >> 1);
        unsigned c = 0;
        #pragma unroll
        for (int i = 0; i < 32; ++i) c += (key[i] >= mid) ? 1u : 0u;
        c = __reduce_add_sync(0xFFFFFFFFu, c);
        if (c >= (unsigned)KSP) lo = mid; else hi = mid - 1u;
    }
    unsigned T = lo;

    // ---- softmax over selected (excluded get exactly 0, matching exp(-1e9)) ----
    float lsum = 0.f;
    #pragma unroll
    for (int i = 0; i < 32; ++i) {
        float e = 0.f;
        if (key[i] >= T) {
            unsigned ub = key[i];
            unsigned fb = ub ^ ((ub & 0x80000000u) ? 0x80000000u : 0xFFFFFFFFu);
            e = __expf(__uint_as_float(fb) - lmax);
        }
        lsum += e;
        srow[lane + 32*i] = e;
    }
    #pragma unroll
    for (int o = 16; o; o >>= 1) lsum += __shfl_xor_sync(0xFFFFFFFFu, lsum, o);
    float inv = 1.f / lsum;
    #pragma unroll
    for (int i = 0; i < 32; ++i) srow[lane + 32*i] *= inv;

    // ---- Phase 2: out = P @ V (warp-uniform skip of zero probabilities) ----
    float o0 = 0.f, o1 = 0.f;
    for (int kt = 0; kt < 8; ++kt) {
        __syncthreads();
        #pragma unroll
        for (int it = 0; it < 4; ++it) {
            int idx = tid + it * 512;
            int keyi = idx >> 4;
            int c    = idx & 15;
            float4 vv = ((const float4*)(Vp + (size_t)(kt*128 + keyi) * 64))[c];
            *(float4*)&sKV[keyi*68 + c*4] = vv;
        }
        __syncthreads();
        const float* pr = &sS[w*1024 + kt*128];
        #pragma unroll 4
        for (int m = 0; m < 128; ++m) {
            float p = pr[m];                 // broadcast -> warp-uniform branch
            if (p != 0.f) {
                o0 = fmaf(p, sKV[m*68 + lane     ], o0);
                o1 = fmaf(p, sKV[m*68 + lane + 32], o1);
            }
        }
    }
    int bb = bh >> 4, hh = bh & 15;
    int nn = n0 + w;
    float* dst = g_attn + ((size_t)(bb*1024 + nn)) * 1024 + hh*64;
    dst[lane]      = o0;
    dst[lane + 32] = o1;
}

// ---------------- launch --------------------------------------------------
extern "C" void kernel_launch(void* const* d_in, const int* in_sizes, int n_in,
                              void* d_out, int out_size)
{
    (void)in_sizes; (void)n_in; (void)out_size;
    const float* x      = (const float*)d_in[0];
    const float* ln1_w  = (const float*)d_in[1];
    const float* ln1_b  = (const float*)d_in[2];
    const float* qkv_w  = (const float*)d_in[3];
    const float* qkv_b  = (const float*)d_in[4];
    const float* out_w  = (const float*)d_in[5];
    const float* out_b  = (const float*)d_in[6];
    const float* ln2_w  = (const float*)d_in[7];
    const float* ln2_b  = (const float*)d_in[8];
    const float* w1     = (const float*)d_in[9];
    const float* b1     = (const float*)d_in[10];
    const float* w2     = (const float*)d_in[11];
    const float* b2     = (const float*)d_in[12];
    const float* mask1  = (const float*)d_in[13];
    const float* mask2  = (const float*)d_in[14];
    float* out = (float*)d_out;

    float *p_xn, *p_attn, *p_x1, *p_hn, *p_h1;
    cudaGetSymbolAddress((void**)&p_xn,   g_xn);
    cudaGetSymbolAddress((void**)&p_attn, g_attn);
    cudaGetSymbolAddress((void**)&p_x1,   g_x1);
    cudaGetSymbolAddress((void**)&p_hn,   g_hn);
    cudaGetSymbolAddress((void**)&p_h1,   g_h1);

    cudaFuncSetAttribute(attn_kernel,
                         cudaFuncAttributeMaxDynamicSharedMemorySize, ATTN_SMEM);

    // 1) LN1
    ln_kernel<<<M_, 256>>>(x, ln1_w, ln1_b, p_xn);
    // 2) QKV projection (scatter into q/k/v)
    gemm_nt<0><<<dim3(3*C_/128, M_/128), 256>>>(p_xn, qkv_w, qkv_b,
                                                nullptr, nullptr, nullptr,
                                                M_, 3*C_, C_);
    // 3) sparse attention
    attn_kernel<<<BH_*(N_/16), 512, ATTN_SMEM>>>();
    // 4) output projection + residual
    gemm_nt<1><<<dim3(C_/128, M_/128), 256>>>(p_attn, out_w, out_b,
                                              nullptr, x, p_x1,
                                              M_, C_, C_);
    // 5) LN2
    ln_kernel<<<M_, 256>>>(p_x1, ln2_w, ln2_b, p_hn);
    // 6) FFN1: relu((hn @ w1^T + b1) * m1)
    gemm_nt<2><<<dim3(FF_/128, M_/128), 256>>>(p_hn, w1, b1,
                                               mask1, nullptr, p_h1,
                                               M_, FF_, C_);
    // 7) FFN2: x1 + (h1 @ w2^T + b2) * m2  -> d_out
    gemm_nt<3><<<dim3(C_/128, M_/128), 256>>>(p_h1, w2, b2,
                                              mask2, p_x1, out,
                                              M_, C_, FF_);
}

// round 4
// speedup vs baseline: 1.6264x; 1.6222x over previous
#include <cuda_runtime.h>
#include <cuda_bf16.h>
#include <stdint.h>

#define B_   8
#define N_   1024
#define C_   1024
#define HD_  64
#define FF_  4096
#define BH_  128
#define M_   8192
#define KSP  102

typedef __nv_bfloat16 bf16;
typedef __nv_bfloat162 bf162;

// ---------------- scratch ----------------
__device__ __align__(256) float g_q[(size_t)BH_*N_*HD_];
__device__ __align__(256) float g_k[(size_t)BH_*N_*HD_];
__device__ __align__(256) float g_v[(size_t)BH_*N_*HD_];
__device__ __align__(256) float g_x1[(size_t)M_*C_];
__device__ __align__(256) bf16 g_xnh[(size_t)M_*C_],  g_xnl[(size_t)M_*C_];
__device__ __align__(256) bf16 g_hnh[(size_t)M_*C_],  g_hnl[(size_t)M_*C_];
__device__ __align__(256) bf16 g_ath[(size_t)M_*C_],  g_atl[(size_t)M_*C_];
__device__ __align__(256) bf16 g_h1h[(size_t)M_*FF_], g_h1l[(size_t)M_*FF_];
__device__ __align__(256) bf16 g_qwh[(size_t)3*C_*C_], g_qwl[(size_t)3*C_*C_];
__device__ __align__(256) bf16 g_owh[(size_t)C_*C_],   g_owl[(size_t)C_*C_];
__device__ __align__(256) bf16 g_w1h[(size_t)FF_*C_],  g_w1l[(size_t)FF_*C_];
__device__ __align__(256) bf16 g_w2h[(size_t)C_*FF_],  g_w2l[(size_t)C_*FF_];

// ---------------- helpers ----------------
__device__ __forceinline__ uint32_t s2u(const void* p) {
    uint32_t a;
    asm("{ .reg .u64 t; cvta.to.shared.u64 t, %1; cvt.u32.u64 %0, t; }" : "=r"(a) : "l"(p));
    return a;
}
__device__ __forceinline__ void bfsplit(float v, bf16& h, bf16& l) {
    h = __float2bfloat16(v);
    l = __float2bfloat16(v - __bfloat162float(h));
}
__device__ __forceinline__ void ldsm4(uint32_t* r, uint32_t a) {
    asm volatile("ldmatrix.sync.aligned.m8n8.x4.shared.b16 {%0,%1,%2,%3}, [%4];"
        : "=r"(r[0]), "=r"(r[1]), "=r"(r[2]), "=r"(r[3]) : "r"(a));
}
__device__ __forceinline__ void ldsm2(uint32_t* r, uint32_t a) {
    asm volatile("ldmatrix.sync.aligned.m8n8.x2.shared.b16 {%0,%1}, [%2];"
        : "=r"(r[0]), "=r"(r[1]) : "r"(a));
}
__device__ __forceinline__ void mma16816(float* c, const uint32_t* a, const uint32_t* b) {
    asm volatile("mma.sync.aligned.m16n8k16.row.col.f32.bf16.bf16.f32 "
        "{%0,%1,%2,%3}, {%4,%5,%6,%7}, {%8,%9}, {%0,%1,%2,%3};"
        : "+f"(c[0]), "+f"(c[1]), "+f"(c[2]), "+f"(c[3])
        : "r"(a[0]), "r"(a[1]), "r"(a[2]), "r"(a[3]), "r"(b[0]), "r"(b[1]));
}
#define CP_ASYNC16(s, g) \
    asm volatile("cp.async.cg.shared.global [%0], [%1], 16;" :: "r"(s), "l"(g))
#define CP_COMMIT() asm volatile("cp.async.commit_group;" ::: "memory")

// ---------------- weight split ----------------
__global__ void __launch_bounds__(256)
cvt_split(const float* __restrict__ s, bf16* __restrict__ h, bf16* __restrict__ l, int n4)
{
    int i = blockIdx.x * 256 + threadIdx.x;
    if (i >= n4) return;
    float4 v = ((const float4*)s)[i];
    bf16 h0,h1,h2,h3,l0,l1,l2,l3;
    bfsplit(v.x,h0,l0); bfsplit(v.y,h1,l1); bfsplit(v.z,h2,l2); bfsplit(v.w,h3,l3);
    bf162 a,b;
    a.x=h0;a.y=h1;b.x=h2;b.y=h3; ((bf162*)h)[i*2]=a; ((bf162*)h)[i*2+1]=b;
    a.x=l0;a.y=l1;b.x=l2;b.y=l3; ((bf162*)l)[i*2]=a; ((bf162*)l)[i*2+1]=b;
}

// ---------------- LayerNorm -> bf16 hi/lo ----------------
__global__ void __launch_bounds__(256)
ln_bf16(const float* __restrict__ x, const float* __restrict__ w,
        const float* __restrict__ b, bf16* __restrict__ yh, bf16* __restrict__ yl)
{
    __shared__ float red[16];
    int row = blockIdx.x, t = threadIdx.x;
    float4 v = ((const float4*)(x + (size_t)row * 1024))[t];
    float s  = v.x + v.y + v.z + v.w;
    float ss = v.x*v.x + v.y*v.y + v.z*v.z + v.w*v.w;
    #pragma unroll
    for (int o = 16; o; o >>= 1) {
        s  += __shfl_xor_sync(~0u, s, o);
        ss += __shfl_xor_sync(~0u, ss, o);
    }
    if ((t & 31) == 0) { red[t>>5] = s; red[(t>>5)+8] = ss; }
    __syncthreads();
    if (t == 0) {
        float ts=0.f, tss=0.f;
        #pragma unroll
        for (int i = 0; i < 8; ++i) { ts += red[i]; tss += red[i+8]; }
        float mu = ts * (1.f/1024.f);
        red[0] = mu; red[1] = rsqrtf(tss*(1.f/1024.f) - mu*mu + 1e-5f);
    }
    __syncthreads();
    float mu = red[0], rs = red[1];
    float4 wv = ((const float4*)w)[t];
    float4 bv = ((const float4*)b)[t];
    float o0 = (v.x-mu)*rs*wv.x + bv.x, o1 = (v.y-mu)*rs*wv.y + bv.y;
    float o2 = (v.z-mu)*rs*wv.z + bv.z, o3 = (v.w-mu)*rs*wv.w + bv.w;
    bf16 h0,h1,h2,h3,l0,l1,l2,l3;
    bfsplit(o0,h0,l0); bfsplit(o1,h1,l1); bfsplit(o2,h2,l2); bfsplit(o3,h3,l3);
    size_t oi = ((size_t)row*1024 + t*4) >> 1;
    bf162 pa, pb;
    pa.x=h0;pa.y=h1;pb.x=h2;pb.y=h3; ((bf162*)yh)[oi]=pa; ((bf162*)yh)[oi+1]=pb;
    pa.x=l0;pa.y=l1;pb.x=l2;pb.y=l3; ((bf162*)yl)[oi]=pa; ((bf162*)yl)[oi+1]=pb;
}

// ---------------- HMMA GEMM: 128x128 CTA tile, A@B^T, bf16x3 -> fp32 ------
// smem per stage: Ahi | Alo | Bhi | Blo, each 128 rows x 40 bf16 (80B rows).
#define TILE_B   10240
#define STAGE_B  (4*TILE_B)
#define GSMEM    (3*STAGE_B)

__device__ __forceinline__ void issue_stage(
    const bf16* __restrict__ Ah, const bf16* __restrict__ Al,
    const bf16* __restrict__ Bh, const bf16* __restrict__ Bl,
    uint32_t sbase, int bm, int bn, int ko, int K, int tid)
{
    #pragma unroll
    for (int i = 0; i < 8; ++i) {
        int lin = tid + (i << 8);
        int tile = lin >> 9;
        int wit = lin & 511;
        int r = wit >> 2, ch = wit & 3;
        const bf16* gp;
        if      (tile == 0) gp = Ah + (size_t)(bm + r) * K + ko + ch*8;
        else if (tile == 1) gp = Al + (size_t)(bm + r) * K + ko + ch*8;
        else if (tile == 2) gp = Bh + (size_t)(bn + r) * K + ko + ch*8;
        else                gp = Bl + (size_t)(bn + r) * K + ko + ch*8;
        uint32_t sp = sbase + tile*TILE_B + r*80 + ch*16;
        CP_ASYNC16(sp, gp);
    }
    CP_COMMIT();
}

// EPI 0: QKV scatter(+bias) | 1: +bias+res->outf | 2: bfsplit(relu(acc+b)*(m>.5)) | 3: res+(acc+b)*(m>.5)
template<int EPI>
__global__ void __launch_bounds__(256)
tc_gemm(const bf16* __restrict__ Ah, const bf16* __restrict__ Al,
        const bf16* __restrict__ Bh, const bf16* __restrict__ Bl,
        const float* __restrict__ bias, const float* __restrict__ aux,
        const float* __restrict__ res, float* __restrict__ outf,
        bf16* __restrict__ outh, bf16* __restrict__ outl, int N, int K)
{
    extern __shared__ char smem[];
    uint32_t sb = s2u(smem);
    const int tid = threadIdx.x, lane = tid & 31, wid = tid >> 5;
    const int wm = wid & 3, wn = wid >> 2;
    const int bm = blockIdx.y << 7, bn = blockIdx.x << 7;

    float acc[2][8][4];
    #pragma unroll
    for (int i = 0; i < 2; ++i)
        #pragma unroll
        for (int j = 0; j < 8; ++j)
            #pragma unroll
            for (int q = 0; q < 4; ++q) acc[i][j][q] = 0.f;

    const int ktn = K >> 5;
    issue_stage(Ah, Al, Bh, Bl, sb,           bm, bn, 0,  K, tid);
    issue_stage(Ah, Al, Bh, Bl, sb + STAGE_B, bm, bn, 32, K, tid);

    // ldmatrix per-thread address offsets
    const int a_ro = (lane & 15);        // A row within 16
    const int a_ko = (lane >> 4) * 8;    // A k offset 0/8
    const int b_ro = (lane & 7);         // B row within 8
    const int b_ko = ((lane >> 3) & 1) * 8;

    for (int kt = 0; kt < ktn; ++kt) {
        if (kt + 1 < ktn) asm volatile("cp.async.wait_group 1;" ::: "memory");
        else              asm volatile("cp.async.wait_group 0;" ::: "memory");
        __syncthreads();
        if (kt + 2 < ktn)
            issue_stage(Ah, Al, Bh, Bl, sb + ((kt + 2) % 3) * STAGE_B,
                        bm, bn, (kt + 2) * 32, K, tid);

        uint32_t st = sb + (kt % 3) * STAGE_B;
        #pragma unroll
        for (int ks = 0; ks < 2; ++ks) {
            uint32_t ahi[2][4], alo[2][4];
            #pragma unroll
            for (int mf = 0; mf < 2; ++mf) {
                uint32_t ad = st + (wm*32 + mf*16 + a_ro)*80 + (ks*16 + a_ko)*2;
                ldsm4(ahi[mf], ad);
                ldsm4(alo[mf], ad + TILE_B);
            }
            #pragma unroll
            for (int nf = 0; nf < 8; ++nf) {
                uint32_t bd = st + 2*TILE_B + (wn*64 + nf*8 + b_ro)*80 + (ks*16 + b_ko)*2;
                uint32_t bhi[2], blo[2];
                ldsm2(bhi, bd);
                ldsm2(blo, bd + TILE_B);
                mma16816(acc[0][nf], ahi[0], bhi);
                mma16816(acc[1][nf], ahi[1], bhi);
                mma16816(acc[0][nf], ahi[0], blo);
                mma16816(acc[1][nf], ahi[1], blo);
                mma16816(acc[0][nf], alo[0], bhi);
                mma16816(acc[1][nf], alo[1], bhi);
            }
        }
        __syncthreads();
    }

    // ---- epilogue: direct global stores (float2 granularity) ----
    const int tr = lane >> 2;
    const int tc = (lane & 3) * 2;
    #pragma unroll
    for (int mf = 0; mf < 2; ++mf) {
        #pragma unroll
        for (int nf = 0; nf < 8; ++nf) {
            int gj = bn + wn*64 + nf*8 + tc;
            float2 b2 = *(const float2*)&bias[gj];
            #pragma unroll
            for (int h = 0; h < 2; ++h) {
                int gi = bm + wm*32 + mf*16 + tr + h*8;
                float v0 = acc[mf][nf][h*2]   + b2.x;
                float v1 = acc[mf][nf][h*2+1] + b2.y;
                size_t off = (size_t)gi * N + gj;
                if (EPI == 0) {
                    int wh = gj >> 10, hh = (gj >> 6) & 15, d = gj & 63;
                    int bb = gi >> 10, nn = gi & 1023;
                    float* dst = (wh == 0) ? g_q : ((wh == 1) ? g_k : g_v);
                    float2 o; o.x = v0; o.y = v1;
                    *(float2*)&dst[(((size_t)(bb*16 + hh))*1024 + nn)*64 + d] = o;
                } else if (EPI == 1) {
                    float2 rr = *(const float2*)&res[off];
                    float2 o; o.x = v0 + rr.x; o.y = v1 + rr.y;
                    *(float2*)&outf[off] = o;
                } else if (EPI == 2) {
                    float2 m = *(const float2*)&aux[off];
                    v0 = (m.x > 0.5f) ? fmaxf(v0, 0.f) : 0.f;
                    v1 = (m.y > 0.5f) ? fmaxf(v1, 0.f) : 0.f;
                    bf16 h0,l0,h1,l1;
                    bfsplit(v0,h0,l0); bfsplit(v1,h1,l1);
                    bf162 p; p.x=h0; p.y=h1; *(bf162*)&outh[off] = p;
                    p.x=l0; p.y=l1;          *(bf162*)&outl[off] = p;
                } else {
                    float2 m  = *(const float2*)&aux[off];
                    float2 rr = *(const float2*)&res[off];
                    float2 o;
                    o.x = rr.x + ((m.x > 0.5f) ? v0 : 0.f);
                    o.y = rr.y + ((m.y > 0.5f) ? v1 : 0.f);
                    *(float2*)&outf[off] = o;
                }
            }
        }
    }
}

// ---------------- sparse attention: 32 q-rows/block, 2 rows/warp ----------
#define ATTN_SMEM ((2048 + 128*68 + 32*1024) * 4)

__global__ void __launch_bounds__(512)
attn_kernel()
{
    extern __shared__ float sm[];
    float* sQ  = sm;
    float* sKV = sm + 2048;
    float* sS  = sm + 2048 + 8704;

    int blk = blockIdx.x, bh = blk >> 5, n0 = (blk & 31) << 5;
    const float* Q  = g_q + (size_t)bh * (N_*HD_);
    const float* Kp = g_k + (size_t)bh * (N_*HD_);
    const float* Vp = g_v + (size_t)bh * (N_*HD_);
    int tid = threadIdx.x, lane = tid & 31, w = tid >> 5;
    int r0 = 2 * w;

    ((float4*)sQ)[tid] = ((const float4*)(Q + (size_t)n0 * HD_))[tid];

    for (int kt = 0; kt < 8; ++kt) {
        __syncthreads();
        #pragma unroll
        for (int it = 0; it < 4; ++it) {
            int idx = tid + it*512, ky = idx >> 4, c = idx & 15;
            float4 kv = ((const float4*)(Kp + (size_t)(kt*128 + ky) * 64))[c];
            *(float4*)&sKV[ky*68 + c*4] = kv;
        }
        __syncthreads();
        float a0=0,a1=0,a2=0,a3=0, c0=0,c1=0,c2=0,c3=0;
        const float4* qa = (const float4*)&sQ[r0 * 64];
        #pragma unroll
        for (int c = 0; c < 16; ++c) {
            float4 qv = qa[c], qw = qa[c + 16];
            float4 k0 = *(const float4*)&sKV[(lane     )*68 + c*4];
            float4 k1 = *(const float4*)&sKV[(lane + 32)*68 + c*4];
            float4 k2 = *(const float4*)&sKV[(lane + 64)*68 + c*4];
            float4 k3 = *(const float4*)&sKV[(lane + 96)*68 + c*4];
            a0 = fmaf(qv.x,k0.x,fmaf(qv.y,k0.y,fmaf(qv.z,k0.z,fmaf(qv.w,k0.w,a0))));
            a1 = fmaf(qv.x,k1.x,fmaf(qv.y,k1.y,fmaf(qv.z,k1.z,fmaf(qv.w,k1.w,a1))));
            a2 = fmaf(qv.x,k2.x,fmaf(qv.y,k2.y,fmaf(qv.z,k2.z,fmaf(qv.w,k2.w,a2))));
            a3 = fmaf(qv.x,k3.x,fmaf(qv.y,k3.y,fmaf(qv.z,k3.z,fmaf(qv.w,k3.w,a3))));
            c0 = fmaf(qw.x,k0.x,fmaf(qw.y,k0.y,fmaf(qw.z,k0.z,fmaf(qw.w,k0.w,c0))));
            c1 = fmaf(qw.x,k1.x,fmaf(qw.y,k1.y,fmaf(qw.z,k1.z,fmaf(qw.w,k1.w,c1))));
            c2 = fmaf(qw.x,k2.x,fmaf(qw.y,k2.y,fmaf(qw.z,k2.z,fmaf(qw.w,k2.w,c2))));
            c3 = fmaf(qw.x,k3.x,fmaf(qw.y,k3.y,fmaf(qw.z,k3.z,fmaf(qw.w,k3.w,c3))));
        }
        float* sa = &sS[r0*1024 + kt*128];
        float* sbr = sa + 1024;
        sa[lane]=a0*0.125f; sa[lane+32]=a1*0.125f; sa[lane+64]=a2*0.125f; sa[lane+96]=a3*0.125f;
        sbr[lane]=c0*0.125f; sbr[lane+32]=c1*0.125f; sbr[lane+64]=c2*0.125f; sbr[lane+96]=c3*0.125f;
    }

    #pragma unroll 1
    for (int rr = 0; rr < 2; ++rr) {
        float* srow = &sS[(r0 + rr) * 1024];
        unsigned key[32];
        float lmax = -3.4e38f;
        #pragma unroll
        for (int i = 0; i < 32; ++i) {
            float s = srow[lane + 32*i];
            lmax = fmaxf(lmax, s);
            unsigned ub = __float_as_uint(s);
            key[i] = ub ^ (((unsigned)((int)ub >> 31)) | 0x80000000u);
        }
        #pragma unroll
        for (int o = 16; o; o >>= 1) lmax = fmaxf(lmax, __shfl_xor_sync(~0u, lmax, o));
        unsigned lo = 0u, hi = 0xFFFFFFFFu;
        while (lo < hi) {
            unsigned mid = lo + (unsigned)(((unsigned long long)(hi - lo) + 1ull) >> 1);
            unsigned c = 0;
            #pragma unroll
            for (int i = 0; i < 32; ++i) c += (key[i] >= mid) ? 1u : 0u;
            c = __reduce_add_sync(~0u, c);
            if (c >= (unsigned)KSP) lo = mid; else hi = mid - 1u;
        }
        unsigned T = lo;
        float lsum = 0.f;
        #pragma unroll
        for (int i = 0; i < 32; ++i) {
            float e = 0.f;
            if (key[i] >= T) {
                unsigned ub = key[i];
                unsigned fb = ub ^ ((ub & 0x80000000u) ? 0x80000000u : 0xFFFFFFFFu);
                e = __expf(__uint_as_float(fb) - lmax);
            }
            lsum += e;
            srow[lane + 32*i] = e;
        }
        #pragma unroll
        for (int o = 16; o; o >>= 1) lsum += __shfl_xor_sync(~0u, lsum, o);
        float inv = 1.f / lsum;
        #pragma unroll
        for (int i = 0; i < 32; ++i) srow[lane + 32*i] *= inv;
    }

    float o00=0, o01=0, o10=0, o11=0;
    for (int kt = 0; kt < 8; ++kt) {
        __syncthreads();
        #pragma unroll
        for (int it = 0; it < 4; ++it) {
            int idx = tid + it*512, ky = idx >> 4, c = idx & 15;
            float4 vv = ((const float4*)(Vp + (size_t)(kt*128 + ky) * 64))[c];
            *(float4*)&sKV[ky*68 + c*4] = vv;
        }
        __syncthreads();
        const float* pa = &sS[r0*1024 + kt*128];
        const float* pb = pa + 1024;
        #pragma unroll 4
        for (int m = 0; m < 128; ++m) {
            float x0 = pa[m];
            if (x0 != 0.f) {
                o00 = fmaf(x0, sKV[m*68 + lane     ], o00);
                o01 = fmaf(x0, sKV[m*68 + lane + 32], o01);
            }
            float x1 = pb[m];
            if (x1 != 0.f) {
                o10 = fmaf(x1, sKV[m*68 + lane     ], o10);
                o11 = fmaf(x1, sKV[m*68 + lane + 32], o11);
            }
        }
    }
    int bb = bh >> 4, hh = bh & 15;
    #pragma unroll
    for (int rr = 0; rr < 2; ++rr) {
        size_t base = ((size_t)(bb*1024 + n0 + r0 + rr)) * 1024 + hh*64;
        bf16 h, l;
        bfsplit(rr ? o10 : o00, h, l);
        g_ath[base + lane] = h; g_atl[base + lane] = l;
        bfsplit(rr ? o11 : o01, h, l);
        g_ath[base + lane + 32] = h; g_atl[base + lane + 32] = l;
    }
}

// ---------------- launch ----------------
extern "C" void kernel_launch(void* const* d_in, const int* in_sizes, int n_in,
                              void* d_out, int out_size)
{
    (void)in_sizes; (void)n_in; (void)out_size;
    const float* x     = (const float*)d_in[0];
    const float* ln1_w = (const float*)d_in[1];
    const float* ln1_b = (const float*)d_in[2];
    const float* qkv_w = (const float*)d_in[3];
    const float* qkv_b = (const float*)d_in[4];
    const float* out_w = (const float*)d_in[5];
    const float* out_b = (const float*)d_in[6];
    const float* ln2_w = (const float*)d_in[7];
    const float* ln2_b = (const float*)d_in[8];
    const float* w1    = (const float*)d_in[9];
    const float* b1    = (const float*)d_in[10];
    const float* w2    = (const float*)d_in[11];
    const float* b2    = (const float*)d_in[12];
    const float* mask1 = (const float*)d_in[13];
    const float* mask2 = (const float*)d_in[14];
    float* out = (float*)d_out;

    void *x1, *xnh, *xnl, *hnh, *hnl, *ath, *atl, *h1h, *h1l,
         *qwh, *qwl, *owh, *owl, *w1h, *w1l, *w2h, *w2l;
    cudaGetSymbolAddress(&x1, g_x1);
    cudaGetSymbolAddress(&xnh, g_xnh); cudaGetSymbolAddress(&xnl, g_xnl);
    cudaGetSymbolAddress(&hnh, g_hnh); cudaGetSymbolAddress(&hnl, g_hnl);
    cudaGetSymbolAddress(&ath, g_ath); cudaGetSymbolAddress(&atl, g_atl);
    cudaGetSymbolAddress(&h1h, g_h1h); cudaGetSymbolAddress(&h1l, g_h1l);
    cudaGetSymbolAddress(&qwh, g_qwh); cudaGetSymbolAddress(&qwl, g_qwl);
    cudaGetSymbolAddress(&owh, g_owh); cudaGetSymbolAddress(&owl, g_owl);
    cudaGetSymbolAddress(&w1h, g_w1h); cudaGetSymbolAddress(&w1l, g_w1l);
    cudaGetSymbolAddress(&w2h, g_w2h); cudaGetSymbolAddress(&w2l, g_w2l);

    cudaFuncSetAttribute(attn_kernel, cudaFuncAttributeMaxDynamicSharedMemorySize, ATTN_SMEM);
    cudaFuncSetAttribute(tc_gemm<0>, cudaFuncAttributeMaxDynamicSharedMemorySize, GSMEM);
    cudaFuncSetAttribute(tc_gemm<1>, cudaFuncAttributeMaxDynamicSharedMemorySize, GSMEM);
    cudaFuncSetAttribute(tc_gemm<2>, cudaFuncAttributeMaxDynamicSharedMemorySize, GSMEM);
    cudaFuncSetAttribute(tc_gemm<3>, cudaFuncAttributeMaxDynamicSharedMemorySize, GSMEM);

    cvt_split<<<3072, 256>>>(qkv_w, (bf16*)qwh, (bf16*)qwl, 786432);
    cvt_split<<<1024, 256>>>(out_w, (bf16*)owh, (bf16*)owl, 262144);
    cvt_split<<<4096, 256>>>(w1,    (bf16*)w1h, (bf16*)w1l, 1048576);
    cvt_split<<<4096, 256>>>(w2,    (bf16*)w2h, (bf16*)w2l, 1048576);

    ln_bf16<<<M_, 256>>>(x, ln1_w, ln1_b, (bf16*)xnh, (bf16*)xnl);

    tc_gemm<0><<<dim3(24, 64), 256, GSMEM>>>((bf16*)xnh, (bf16*)xnl,
        (bf16*)qwh, (bf16*)qwl, qkv_b, nullptr, nullptr, nullptr, nullptr, nullptr,
        3*C_, C_);

    attn_kernel<<<BH_*(N_/32), 512, ATTN_SMEM>>>();

    tc_gemm<1><<<dim3(8, 64), 256, GSMEM>>>((bf16*)ath, (bf16*)atl,
        (bf16*)owh, (bf16*)owl, out_b, nullptr, x, (float*)x1, nullptr, nullptr,
        C_, C_);

    ln_bf16<<<M_, 256>>>((float*)x1, ln2_w, ln2_b, (bf16*)hnh, (bf16*)hnl);

    tc_gemm<2><<<dim3(32, 64), 256, GSMEM>>>((bf16*)hnh, (bf16*)hnl,
        (bf16*)w1h, (bf16*)w1l, b1, mask1, nullptr, nullptr, (bf16*)h1h, (bf16*)h1l,
        FF_, C_);

    tc_gemm<3><<<dim3(8, 64), 256, GSMEM>>>((bf16*)h1h, (bf16*)h1l,
        (bf16*)w2h, (bf16*)w2l, b2, mask2, (float*)x1, out, nullptr, nullptr,
        C_, FF_);
}

// round 5
// speedup vs baseline: 1.8500x; 1.1374x over previous
#include <cuda_runtime.h>
#include <cuda_bf16.h>
#include <stdint.h>

#define B_   8
#define N_   1024
#define C_   1024
#define HD_  64
#define FF_  4096
#define BH_  128
#define M_   8192
#define KSP  102

typedef __nv_bfloat16 bf16;
typedef __nv_bfloat162 bf162;

// ---------------- scratch ----------------
__device__ __align__(256) float g_v[(size_t)BH_*N_*HD_];
__device__ __align__(256) float g_x1[(size_t)M_*C_];
__device__ __align__(256) bf16 g_qh[(size_t)BH_*N_*HD_], g_ql[(size_t)BH_*N_*HD_];
__device__ __align__(256) bf16 g_kh[(size_t)BH_*N_*HD_], g_kl[(size_t)BH_*N_*HD_];
__device__ __align__(256) bf16 g_xnh[(size_t)M_*C_],  g_xnl[(size_t)M_*C_];
__device__ __align__(256) bf16 g_hnh[(size_t)M_*C_],  g_hnl[(size_t)M_*C_];
__device__ __align__(256) bf16 g_ath[(size_t)M_*C_],  g_atl[(size_t)M_*C_];
__device__ __align__(256) bf16 g_h1h[(size_t)M_*FF_], g_h1l[(size_t)M_*FF_];
__device__ __align__(256) bf16 g_qwh[(size_t)3*C_*C_], g_qwl[(size_t)3*C_*C_];
__device__ __align__(256) bf16 g_owh[(size_t)C_*C_],   g_owl[(size_t)C_*C_];
__device__ __align__(256) bf16 g_w1h[(size_t)FF_*C_],  g_w1l[(size_t)FF_*C_];
__device__ __align__(256) bf16 g_w2h[(size_t)C_*FF_],  g_w2l[(size_t)C_*FF_];

// ---------------- helpers ----------------
__device__ __forceinline__ uint32_t s2u(const void* p) {
    uint32_t a;
    asm("{ .reg .u64 t; cvta.to.shared.u64 t, %1; cvt.u32.u64 %0, t; }" : "=r"(a) : "l"(p));
    return a;
}
__device__ __forceinline__ void bfsplit(float v, bf16& h, bf16& l) {
    h = __float2bfloat16(v);
    l = __float2bfloat16(v - __bfloat162float(h));
}
__device__ __forceinline__ void ldsm4(uint32_t* r, uint32_t a) {
    asm volatile("ldmatrix.sync.aligned.m8n8.x4.shared.b16 {%0,%1,%2,%3}, [%4];"
        : "=r"(r[0]), "=r"(r[1]), "=r"(r[2]), "=r"(r[3]) : "r"(a));
}
__device__ __forceinline__ void mma16816(float* c, const uint32_t* a, const uint32_t* b) {
    asm volatile("mma.sync.aligned.m16n8k16.row.col.f32.bf16.bf16.f32 "
        "{%0,%1,%2,%3}, {%4,%5,%6,%7}, {%8,%9}, {%0,%1,%2,%3};"
        : "+f"(c[0]), "+f"(c[1]), "+f"(c[2]), "+f"(c[3])
        : "r"(a[0]), "r"(a[1]), "r"(a[2]), "r"(a[3]), "r"(b[0]), "r"(b[1]));
}
#define CP_ASYNC16(s, g) \
    asm volatile("cp.async.cg.shared.global [%0], [%1], 16;" :: "r"(s), "l"(g))
#define CP_COMMIT() asm volatile("cp.async.commit_group;" ::: "memory")

// ---------------- weight split ----------------
__global__ void __launch_bounds__(256)
cvt_split(const float* __restrict__ s, bf16* __restrict__ h, bf16* __restrict__ l, int n4)
{
    int i = blockIdx.x * 256 + threadIdx.x;
    if (i >= n4) return;
    float4 v = ((const float4*)s)[i];
    bf16 h0,h1,h2,h3,l0,l1,l2,l3;
    bfsplit(v.x,h0,l0); bfsplit(v.y,h1,l1); bfsplit(v.z,h2,l2); bfsplit(v.w,h3,l3);
    bf162 a,b;
    a.x=h0;a.y=h1;b.x=h2;b.y=h3; ((bf162*)h)[i*2]=a; ((bf162*)h)[i*2+1]=b;
    a.x=l0;a.y=l1;b.x=l2;b.y=l3; ((bf162*)l)[i*2]=a; ((bf162*)l)[i*2+1]=b;
}

// ---------------- LayerNorm -> bf16 hi/lo ----------------
__global__ void __launch_bounds__(256)
ln_bf16(const float* __restrict__ x, const float* __restrict__ w,
        const float* __restrict__ b, bf16* __restrict__ yh, bf16* __restrict__ yl)
{
    __shared__ float red[16];
    int row = blockIdx.x, t = threadIdx.x;
    float4 v = ((const float4*)(x + (size_t)row * 1024))[t];
    float s  = v.x + v.y + v.z + v.w;
    float ss = v.x*v.x + v.y*v.y + v.z*v.z + v.w*v.w;
    #pragma unroll
    for (int o = 16; o; o >>= 1) {
        s  += __shfl_xor_sync(~0u, s, o);
        ss += __shfl_xor_sync(~0u, ss, o);
    }
    if ((t & 31) == 0) { red[t>>5] = s; red[(t>>5)+8] = ss; }
    __syncthreads();
    if (t == 0) {
        float ts=0.f, tss=0.f;
        #pragma unroll
        for (int i = 0; i < 8; ++i) { ts += red[i]; tss += red[i+8]; }
        float mu = ts * (1.f/1024.f);
        red[0] = mu; red[1] = rsqrtf(tss*(1.f/1024.f) - mu*mu + 1e-5f);
    }
    __syncthreads();
    float mu = red[0], rs = red[1];
    float4 wv = ((const float4*)w)[t];
    float4 bv = ((const float4*)b)[t];
    float o0 = (v.x-mu)*rs*wv.x + bv.x, o1 = (v.y-mu)*rs*wv.y + bv.y;
    float o2 = (v.z-mu)*rs*wv.z + bv.z, o3 = (v.w-mu)*rs*wv.w + bv.w;
    bf16 h0,h1,h2,h3,l0,l1,l2,l3;
    bfsplit(o0,h0,l0); bfsplit(o1,h1,l1); bfsplit(o2,h2,l2); bfsplit(o3,h3,l3);
    size_t oi = ((size_t)row*1024 + t*4) >> 1;
    bf162 pa, pb;
    pa.x=h0;pa.y=h1;pb.x=h2;pb.y=h3; ((bf162*)yh)[oi]=pa; ((bf162*)yh)[oi+1]=pb;
    pa.x=l0;pa.y=l1;pb.x=l2;pb.y=l3; ((bf162*)yl)[oi]=pa; ((bf162*)yl)[oi+1]=pb;
}

// ---------------- HMMA GEMM: 128x128 tile, 512 thr, bf16x3 -> fp32 -------
#define TILE_B   10240
#define STAGE_B  (4*TILE_B)
#define GSMEM    (3*STAGE_B)

__device__ __forceinline__ void issue_stage(
    const bf16* __restrict__ Ah, const bf16* __restrict__ Al,
    const bf16* __restrict__ Bh, const bf16* __restrict__ Bl,
    uint32_t sbase, int bm, int bn, int ko, int K, int tid)
{
    #pragma unroll
    for (int i = 0; i < 4; ++i) {
        int lin = tid + (i << 9);
        int tile = lin >> 9;
        int wit = lin & 511;
        int r = wit >> 2, ch = wit & 3;
        const bf16* gp;
        if      (tile == 0) gp = Ah + (size_t)(bm + r) * K + ko + ch*8;
        else if (tile == 1) gp = Al + (size_t)(bm + r) * K + ko + ch*8;
        else if (tile == 2) gp = Bh + (size_t)(bn + r) * K + ko + ch*8;
        else                gp = Bl + (size_t)(bn + r) * K + ko + ch*8;
        CP_ASYNC16(sbase + tile*TILE_B + r*80 + ch*16, gp);
    }
    CP_COMMIT();
}

// EPI 0: QKV scatter(+bias) q/k->bf16 hi/lo, v->f32 | 1: +bias+res->outf
// EPI 2: bfsplit(relu(acc+b)*(m>.5)) | 3: res+(acc+b)*(m>.5)
template<int EPI>
__global__ void __launch_bounds__(512)
tc_gemm(const bf16* __restrict__ Ah, const bf16* __restrict__ Al,
        const bf16* __restrict__ Bh, const bf16* __restrict__ Bl,
        const float* __restrict__ bias, const float* __restrict__ aux,
        const float* __restrict__ res, float* __restrict__ outf,
        bf16* __restrict__ outh, bf16* __restrict__ outl, int N, int K)
{
    extern __shared__ char smem[];
    uint32_t sb = s2u(smem);
    const int tid = threadIdx.x, lane = tid & 31, wid = tid >> 5;
    const int wm = wid & 3, wn = wid >> 2;
    const int bm = blockIdx.y << 7, bn = blockIdx.x << 7;

    float acc[2][4][4];
    #pragma unroll
    for (int i = 0; i < 2; ++i)
        #pragma unroll
        for (int j = 0; j < 4; ++j)
            #pragma unroll
            for (int q = 0; q < 4; ++q) acc[i][j][q] = 0.f;

    const int ktn = K >> 5;
    issue_stage(Ah, Al, Bh, Bl, sb,           bm, bn, 0,  K, tid);
    issue_stage(Ah, Al, Bh, Bl, sb + STAGE_B, bm, bn, 32, K, tid);

    const int a_ro = (lane & 15);
    const int a_ko = (lane >> 4) * 8;
    const int b_rp = ((lane >> 4) & 1) * 8 + (lane & 7);
    const int b_ko = ((lane >> 3) & 1) * 8;

    for (int kt = 0; kt < ktn; ++kt) {
        if (kt + 1 < ktn) asm volatile("cp.async.wait_group 1;" ::: "memory");
        else              asm volatile("cp.async.wait_group 0;" ::: "memory");
        __syncthreads();
        if (kt + 2 < ktn)
            issue_stage(Ah, Al, Bh, Bl, sb + ((kt + 2) % 3) * STAGE_B,
                        bm, bn, (kt + 2) * 32, K, tid);

        uint32_t st = sb + (kt % 3) * STAGE_B;
        #pragma unroll
        for (int ks = 0; ks < 2; ++ks) {
            uint32_t ahi[2][4], alo[2][4];
            #pragma unroll
            for (int mf = 0; mf < 2; ++mf) {
                uint32_t ad = st + (wm*32 + mf*16 + a_ro)*80 + (ks*16 + a_ko)*2;
                ldsm4(ahi[mf], ad);
                ldsm4(alo[mf], ad + TILE_B);
            }
            uint32_t bhi[8], blo[8];
            #pragma unroll
            for (int np = 0; np < 2; ++np) {
                uint32_t bd = st + 2*TILE_B + (wn*32 + np*16 + b_rp)*80 + (ks*16 + b_ko)*2;
                ldsm4(&bhi[np*4], bd);
                ldsm4(&blo[np*4], bd + TILE_B);
            }
            #pragma unroll
            for (int mf = 0; mf < 2; ++mf)
                #pragma unroll
                for (int nf = 0; nf < 4; ++nf)
                    mma16816(acc[mf][nf], ahi[mf], &bhi[nf*2]);
            #pragma unroll
            for (int mf = 0; mf < 2; ++mf)
                #pragma unroll
                for (int nf = 0; nf < 4; ++nf)
                    mma16816(acc[mf][nf], ahi[mf], &blo[nf*2]);
            #pragma unroll
            for (int mf = 0; mf < 2; ++mf)
                #pragma unroll
                for (int nf = 0; nf < 4; ++nf)
                    mma16816(acc[mf][nf], alo[mf], &bhi[nf*2]);
        }
        __syncthreads();
    }

    const int tr = lane >> 2;
    const int tc = (lane & 3) * 2;
    #pragma unroll
    for (int mf = 0; mf < 2; ++mf) {
        #pragma unroll
        for (int nf = 0; nf < 4; ++nf) {
            int gj = bn + wn*32 + nf*8 + tc;
            float2 b2 = *(const float2*)&bias[gj];
            #pragma unroll
            for (int h = 0; h < 2; ++h) {
                int gi = bm + wm*32 + mf*16 + tr + h*8;
                float v0 = acc[mf][nf][h*2]   + b2.x;
                float v1 = acc[mf][nf][h*2+1] + b2.y;
                size_t off = (size_t)gi * N + gj;
                if (EPI == 0) {
                    int wh = gj >> 10, hh = (gj >> 6) & 15, d = gj & 63;
                    int bb = gi >> 10, nn = gi & 1023;
                    size_t idx = (((size_t)(bb*16 + hh))*1024 + nn)*64 + d;
                    if (wh == 2) {
                        float2 o; o.x = v0; o.y = v1;
                        *(float2*)&g_v[idx] = o;
                    } else {
                        bf16 h0,l0,h1,l1;
                        bfsplit(v0,h0,l0); bfsplit(v1,h1,l1);
                        bf162 ph, pl; ph.x=h0; ph.y=h1; pl.x=l0; pl.y=l1;
                        if (wh == 0) { *(bf162*)&g_qh[idx]=ph; *(bf162*)&g_ql[idx]=pl; }
                        else         { *(bf162*)&g_kh[idx]=ph; *(bf162*)&g_kl[idx]=pl; }
                    }
                } else if (EPI == 1) {
                    float2 rr = *(const float2*)&res[off];
                    float2 o; o.x = v0 + rr.x; o.y = v1 + rr.y;
                    *(float2*)&outf[off] = o;
                } else if (EPI == 2) {
                    float2 m = *(const float2*)&aux[off];
                    v0 = (m.x > 0.5f) ? fmaxf(v0, 0.f) : 0.f;
                    v1 = (m.y > 0.5f) ? fmaxf(v1, 0.f) : 0.f;
                    bf16 h0,l0,h1,l1;
                    bfsplit(v0,h0,l0); bfsplit(v1,h1,l1);
                    bf162 p; p.x=h0; p.y=h1; *(bf162*)&outh[off] = p;
                    p.x=l0; p.y=l1;          *(bf162*)&outl[off] = p;
                } else {
                    float2 m  = *(const float2*)&aux[off];
                    float2 rr = *(const float2*)&res[off];
                    float2 o;
                    o.x = rr.x + ((m.x > 0.5f) ? v0 : 0.f);
                    o.y = rr.y + ((m.y > 0.5f) ? v1 : 0.f);
                    *(float2*)&outf[off] = o;
                }
            }
        }
    }
}

// ---------------- sparse attention: HMMA scores + scalar sparse PV --------
// smem: Q bf16 hi/lo (32x72 rows, 144B stride) | K hi/lo (128x144B x2) / V f32 | sS 32x1034 f32
#define SS_STR  1034
#define ATTN_SMEM (46080 + 32*SS_STR*4)

__global__ void __launch_bounds__(512)
attn_kernel()
{
    extern __shared__ char smraw[];
    float* smf = (float*)smraw;
    uint32_t sb = s2u(smraw);

    int blk = blockIdx.x, bh = blk >> 5, n0 = (blk & 31) << 5;
    int tid = threadIdx.x, lane = tid & 31, w = tid >> 5;
    const size_t bhoff = (size_t)bh * 65536;

    // ---- load Q tile (bf16 hi/lo) ----
    {
        int tile = tid >> 8, wit = tid & 255, r = wit >> 3, ch = wit & 7;
        const bf16* gsrc = (tile ? g_ql : g_qh) + bhoff + (size_t)(n0 + r)*64 + ch*8;
        *(uint4*)(smraw + tile*4608 + r*144 + ch*16) = *(const uint4*)gsrc;
    }
    __syncthreads();

    // ---- preload Q fragments ----
    const int wm = w & 1, wn = w >> 1;
    const int a_ro = lane & 15, a_ko = (lane >> 4) * 8;
    const int b_rp = ((lane >> 4) & 1) * 8 + (lane & 7);
    const int b_ko = ((lane >> 3) & 1) * 8;
    uint32_t qhi[4][4], qlo[4][4];
    #pragma unroll
    for (int ks = 0; ks < 4; ++ks) {
        uint32_t qa = sb + (wm*16 + a_ro)*144 + (ks*16 + a_ko)*2;
        ldsm4(qhi[ks], qa);
        ldsm4(qlo[ks], qa + 4608);
    }
    const int tr = lane >> 2, tc = (lane & 3) * 2;

    // ---- phase 1: S = Q K^T * scale via HMMA ----
    for (int kt = 0; kt < 8; ++kt) {
        __syncthreads();
        #pragma unroll
        for (int i = 0; i < 4; ++i) {
            int lin = tid + (i << 9);
            int tile = (lin >> 10) & 1, wit = lin & 1023;
            int r = wit >> 3, ch = wit & 7;
            const bf16* gsrc = (tile ? g_kl : g_kh) + bhoff + (size_t)(kt*128 + r)*64 + ch*8;
            *(uint4*)(smraw + 9216 + tile*18432 + r*144 + ch*16) = *(const uint4*)gsrc;
        }
        __syncthreads();
        float acc[2][4];
        #pragma unroll
        for (int nf = 0; nf < 2; ++nf)
            #pragma unroll
            for (int q = 0; q < 4; ++q) acc[nf][q] = 0.f;
        #pragma unroll
        for (int ks = 0; ks < 4; ++ks) {
            uint32_t bd = sb + 9216 + (wn*16 + b_rp)*144 + (ks*16 + b_ko)*2;
            uint32_t bhi[4], blo[4];
            ldsm4(bhi, bd);
            ldsm4(blo, bd + 18432);
            mma16816(acc[0], qhi[ks], &bhi[0]);
            mma16816(acc[1], qhi[ks], &bhi[2]);
            mma16816(acc[0], qhi[ks], &blo[0]);
            mma16816(acc[1], qhi[ks], &blo[2]);
            mma16816(acc[0], qlo[ks], &bhi[0]);
            mma16816(acc[1], qlo[ks], &bhi[2]);
        }
        #pragma unroll
        for (int nf = 0; nf < 2; ++nf) {
            int key = kt*128 + wn*16 + nf*8 + tc;
            int row0 = wm*16 + tr;
            float2 o;
            o.x = acc[nf][0]*0.125f; o.y = acc[nf][1]*0.125f;
            *(float2*)&smf[11520 + row0*SS_STR + key] = o;
            o.x = acc[nf][2]*0.125f; o.y = acc[nf][3]*0.125f;
            *(float2*)&smf[11520 + (row0+8)*SS_STR + key] = o;
        }
    }
    __syncthreads();

    // ---- top-k + softmax (2 rows per warp, warp-local) ----
    int r0 = 2 * w;
    #pragma unroll 1
    for (int rr = 0; rr < 2; ++rr) {
        float* srow = &smf[11520 + (r0 + rr) * SS_STR];
        unsigned key[32];
        float lmax = -3.4e38f;
        #pragma unroll
        for (int i = 0; i < 32; ++i) {
            float s = srow[lane + 32*i];
            lmax = fmaxf(lmax, s);
            unsigned ub = __float_as_uint(s);
            key[i] = ub ^ (((unsigned)((int)ub >> 31)) | 0x80000000u);
        }
        #pragma unroll
        for (int o = 16; o; o >>= 1) lmax = fmaxf(lmax, __shfl_xor_sync(~0u, lmax, o));
        unsigned lo = 0u, hi = 0xFFFFFFFFu;
        while (lo < hi) {
            unsigned mid = lo + (unsigned)(((unsigned long long)(hi - lo) + 1ull) >> 1);
            unsigned c = 0;
            #pragma unroll
            for (int i = 0; i < 32; ++i) c += (key[i] >= mid) ? 1u : 0u;
            c = __reduce_add_sync(~0u, c);
            if (c >= (unsigned)KSP) lo = mid; else hi = mid - 1u;
        }
        unsigned T = lo;
        float lsum = 0.f;
        #pragma unroll
        for (int i = 0; i < 32; ++i) {
            float e = 0.f;
            if (key[i] >= T) {
                unsigned ub = key[i];
                unsigned fb = ub ^ ((ub & 0x80000000u) ? 0x80000000u : 0xFFFFFFFFu);
                e = __expf(__uint_as_float(fb) - lmax);
            }
            lsum += e;
            srow[lane + 32*i] = e;
        }
        #pragma unroll
        for (int o = 16; o; o >>= 1) lsum += __shfl_xor_sync(~0u, lsum, o);
        float inv = 1.f / lsum;
        #pragma unroll
        for (int i = 0; i < 32; ++i) srow[lane + 32*i] *= inv;
    }

    // ---- phase 2: P @ V, warp-uniform zero skip ----
    float* sV = smf + 2304;
    float o00=0, o01=0, o10=0, o11=0;
    for (int kt = 0; kt < 8; ++kt) {
        __syncthreads();
        #pragma unroll
        for (int i = 0; i < 4; ++i) {
            int lin = tid + (i << 9);
            int ky = lin >> 4, c = lin & 15;
            float4 vv = *(const float4*)&g_v[bhoff + (size_t)(kt*128 + ky)*64 + c*4];
            *(float4*)&sV[ky*68 + c*4] = vv;
        }
        __syncthreads();
        const float* pa = &smf[11520 + r0*SS_STR + kt*128];
        const float* pb = pa + SS_STR;
        #pragma unroll 4
        for (int m = 0; m < 128; ++m) {
            float x0 = pa[m];
            if (x0 != 0.f) {
                o00 = fmaf(x0, sV[m*68 + lane     ], o00);
                o01 = fmaf(x0, sV[m*68 + lane + 32], o01);
            }
            float x1 = pb[m];
            if (x1 != 0.f) {
                o10 = fmaf(x1, sV[m*68 + lane     ], o10);
                o11 = fmaf(x1, sV[m*68 + lane + 32], o11);
            }
        }
    }
    int bb = bh >> 4, hh = bh & 15;
    #pragma unroll
    for (int rr = 0; rr < 2; ++rr) {
        size_t base = ((size_t)(bb*1024 + n0 + r0 + rr)) * 1024 + hh*64;
        bf16 h, l;
        bfsplit(rr ? o10 : o00, h, l);
        g_ath[base + lane] = h; g_atl[base + lane] = l;
        bfsplit(rr ? o11 : o01, h, l);
        g_ath[base + lane + 32] = h; g_atl[base + lane + 32] = l;
    }
}

// ---------------- launch ----------------
extern "C" void kernel_launch(void* const* d_in, const int* in_sizes, int n_in,
                              void* d_out, int out_size)
{
    (void)in_sizes; (void)n_in; (void)out_size;
    const float* x     = (const float*)d_in[0];
    const float* ln1_w = (const float*)d_in[1];
    const float* ln1_b = (const float*)d_in[2];
    const float* qkv_w = (const float*)d_in[3];
    const float* qkv_b = (const float*)d_in[4];
    const float* out_w = (const float*)d_in[5];
    const float* out_b = (const float*)d_in[6];
    const float* ln2_w = (const float*)d_in[7];
    const float* ln2_b = (const float*)d_in[8];
    const float* w1    = (const float*)d_in[9];
    const float* b1    = (const float*)d_in[10];
    const float* w2    = (const float*)d_in[11];
    const float* b2    = (const float*)d_in[12];
    const float* mask1 = (const float*)d_in[13];
    const float* mask2 = (const float*)d_in[14];
    float* out = (float*)d_out;

    void *x1, *xnh, *xnl, *hnh, *hnl, *ath, *atl, *h1h, *h1l,
         *qwh, *qwl, *owh, *owl, *w1h, *w1l, *w2h, *w2l;
    cudaGetSymbolAddress(&x1, g_x1);
    cudaGetSymbolAddress(&xnh, g_xnh); cudaGetSymbolAddress(&xnl, g_xnl);
    cudaGetSymbolAddress(&hnh, g_hnh); cudaGetSymbolAddress(&hnl, g_hnl);
    cudaGetSymbolAddress(&ath, g_ath); cudaGetSymbolAddress(&atl, g_atl);
    cudaGetSymbolAddress(&h1h, g_h1h); cudaGetSymbolAddress(&h1l, g_h1l);
    cudaGetSymbolAddress(&qwh, g_qwh); cudaGetSymbolAddress(&qwl, g_qwl);
    cudaGetSymbolAddress(&owh, g_owh); cudaGetSymbolAddress(&owl, g_owl);
    cudaGetSymbolAddress(&w1h, g_w1h); cudaGetSymbolAddress(&w1l, g_w1l);
    cudaGetSymbolAddress(&w2h, g_w2h); cudaGetSymbolAddress(&w2l, g_w2l);

    cudaFuncSetAttribute(attn_kernel, cudaFuncAttributeMaxDynamicSharedMemorySize, ATTN_SMEM);
    cudaFuncSetAttribute(tc_gemm<0>, cudaFuncAttributeMaxDynamicSharedMemorySize, GSMEM);
    cudaFuncSetAttribute(tc_gemm<1>, cudaFuncAttributeMaxDynamicSharedMemorySize, GSMEM);
    cudaFuncSetAttribute(tc_gemm<2>, cudaFuncAttributeMaxDynamicSharedMemorySize, GSMEM);
    cudaFuncSetAttribute(tc_gemm<3>, cudaFuncAttributeMaxDynamicSharedMemorySize, GSMEM);

    cvt_split<<<3072, 256>>>(qkv_w, (bf16*)qwh, (bf16*)qwl, 786432);
    cvt_split<<<1024, 256>>>(out_w, (bf16*)owh, (bf16*)owl, 262144);
    cvt_split<<<4096, 256>>>(w1,    (bf16*)w1h, (bf16*)w1l, 1048576);
    cvt_split<<<4096, 256>>>(w2,    (bf16*)w2h, (bf16*)w2l, 1048576);

    ln_bf16<<<M_, 256>>>(x, ln1_w, ln1_b, (bf16*)xnh, (bf16*)xnl);

    tc_gemm<0><<<dim3(24, 64), 512, GSMEM>>>((bf16*)xnh, (bf16*)xnl,
        (bf16*)qwh, (bf16*)qwl, qkv_b, nullptr, nullptr, nullptr, nullptr, nullptr,
        3*C_, C_);

    attn_kernel<<<BH_*(N_/32), 512, ATTN_SMEM>>>();

    tc_gemm<1><<<dim3(8, 64), 512, GSMEM>>>((bf16*)ath, (bf16*)atl,
        (bf16*)owh, (bf16*)owl, out_b, nullptr, x, (float*)x1, nullptr, nullptr,
        C_, C_);

    ln_bf16<<<M_, 256>>>((float*)x1, ln2_w, ln2_b, (bf16*)hnh, (bf16*)hnl);

    tc_gemm<2><<<dim3(32, 64), 512, GSMEM>>>((bf16*)hnh, (bf16*)hnl,
        (bf16*)w1h, (bf16*)w1l, b1, mask1, nullptr, nullptr, (bf16*)h1h, (bf16*)h1l,
        FF_, C_);

    tc_gemm<3><<<dim3(8, 64), 512, GSMEM>>>((bf16*)h1h, (bf16*)h1l,
        (bf16*)w2h, (bf16*)w2l, b2, mask2, (float*)x1, out, nullptr, nullptr,
        C_, FF_);
}

// round 6
// speedup vs baseline: 1.9261x; 1.0412x over previous
#include <cuda_runtime.h>
#include <cuda_bf16.h>
#include <stdint.h>

#define B_   8
#define N_   1024
#define C_   1024
#define HD_  64
#define FF_  4096
#define BH_  128
#define M_   8192
#define KSP  102

typedef __nv_bfloat16 bf16;
typedef __nv_bfloat162 bf162;

// ---------------- scratch ----------------
__device__ __align__(256) float g_v[(size_t)BH_*N_*HD_];
__device__ __align__(256) float g_x1[(size_t)M_*C_];
__device__ __align__(256) bf16 g_qh[(size_t)BH_*N_*HD_], g_ql[(size_t)BH_*N_*HD_];
__device__ __align__(256) bf16 g_kh[(size_t)BH_*N_*HD_], g_kl[(size_t)BH_*N_*HD_];
__device__ __align__(256) bf16 g_xnh[(size_t)M_*C_],  g_xnl[(size_t)M_*C_];
__device__ __align__(256) bf16 g_hnh[(size_t)M_*C_],  g_hnl[(size_t)M_*C_];
__device__ __align__(256) bf16 g_ath[(size_t)M_*C_],  g_atl[(size_t)M_*C_];
__device__ __align__(256) bf16 g_h1h[(size_t)M_*FF_], g_h1l[(size_t)M_*FF_];
__device__ __align__(256) bf16 g_qwh[(size_t)3*C_*C_], g_qwl[(size_t)3*C_*C_];
__device__ __align__(256) bf16 g_owh[(size_t)C_*C_],   g_owl[(size_t)C_*C_];
__device__ __align__(256) bf16 g_w1h[(size_t)FF_*C_],  g_w1l[(size_t)FF_*C_];
__device__ __align__(256) bf16 g_w2h[(size_t)C_*FF_],  g_w2l[(size_t)C_*FF_];

// ---------------- helpers ----------------
__device__ __forceinline__ uint32_t s2u(const void* p) {
    uint32_t a;
    asm("{ .reg .u64 t; cvta.to.shared.u64 t, %1; cvt.u32.u64 %0, t; }" : "=r"(a) : "l"(p));
    return a;
}
__device__ __forceinline__ void bfsplit(float v, bf16& h, bf16& l) {
    h = __float2bfloat16(v);
    l = __float2bfloat16(v - __bfloat162float(h));
}
__device__ __forceinline__ void ldsm4(uint32_t* r, uint32_t a) {
    asm volatile("ldmatrix.sync.aligned.m8n8.x4.shared.b16 {%0,%1,%2,%3}, [%4];"
        : "=r"(r[0]), "=r"(r[1]), "=r"(r[2]), "=r"(r[3]) : "r"(a));
}
__device__ __forceinline__ void mma16816(float* c, const uint32_t* a, const uint32_t* b) {
    asm volatile("mma.sync.aligned.m16n8k16.row.col.f32.bf16.bf16.f32 "
        "{%0,%1,%2,%3}, {%4,%5,%6,%7}, {%8,%9}, {%0,%1,%2,%3};"
        : "+f"(c[0]), "+f"(c[1]), "+f"(c[2]), "+f"(c[3])
        : "r"(a[0]), "r"(a[1]), "r"(a[2]), "r"(a[3]), "r"(b[0]), "r"(b[1]));
}
#define CP_ASYNC16(s, g) \
    asm volatile("cp.async.cg.shared.global [%0], [%1], 16;" :: "r"(s), "l"(g))
#define CP_COMMIT() asm volatile("cp.async.commit_group;" ::: "memory")

// ---------------- weight split (two srcs per launch) ----------------
__global__ void __launch_bounds__(256)
cvt_split2(const float* __restrict__ s0, bf16* __restrict__ h0, bf16* __restrict__ l0, int n0,
           const float* __restrict__ s1, bf16* __restrict__ h1, bf16* __restrict__ l1, int n1)
{
    int i = blockIdx.x * 256 + threadIdx.x;
    const float* s; bf16 *h, *l;
    if (i < n0) { s = s0; h = h0; l = l0; }
    else { i -= n0; if (i >= n1) return; s = s1; h = h1; l = l1; }
    float4 v = ((const float4*)s)[i];
    bf16 h0_,h1_,h2_,h3_,l0_,l1_,l2_,l3_;
    bfsplit(v.x,h0_,l0_); bfsplit(v.y,h1_,l1_); bfsplit(v.z,h2_,l2_); bfsplit(v.w,h3_,l3_);
    bf162 a,b;
    a.x=h0_;a.y=h1_;b.x=h2_;b.y=h3_; ((bf162*)h)[i*2]=a; ((bf162*)h)[i*2+1]=b;
    a.x=l0_;a.y=l1_;b.x=l2_;b.y=l3_; ((bf162*)l)[i*2]=a; ((bf162*)l)[i*2+1]=b;
}

// ---------------- LayerNorm -> bf16 hi/lo ----------------
__global__ void __launch_bounds__(256)
ln_bf16(const float* __restrict__ x, const float* __restrict__ w,
        const float* __restrict__ b, bf16* __restrict__ yh, bf16* __restrict__ yl)
{
    __shared__ float red[16];
    int row = blockIdx.x, t = threadIdx.x;
    float4 v = ((const float4*)(x + (size_t)row * 1024))[t];
    float s  = v.x + v.y + v.z + v.w;
    float ss = v.x*v.x + v.y*v.y + v.z*v.z + v.w*v.w;
    #pragma unroll
    for (int o = 16; o; o >>= 1) {
        s  += __shfl_xor_sync(~0u, s, o);
        ss += __shfl_xor_sync(~0u, ss, o);
    }
    if ((t & 31) == 0) { red[t>>5] = s; red[(t>>5)+8] = ss; }
    __syncthreads();
    if (t == 0) {
        float ts=0.f, tss=0.f;
        #pragma unroll
        for (int i = 0; i < 8; ++i) { ts += red[i]; tss += red[i+8]; }
        float mu = ts * (1.f/1024.f);
        red[0] = mu; red[1] = rsqrtf(tss*(1.f/1024.f) - mu*mu + 1e-5f);
    }
    __syncthreads();
    float mu = red[0], rs = red[1];
    float4 wv = ((const float4*)w)[t];
    float4 bv = ((const float4*)b)[t];
    float o0 = (v.x-mu)*rs*wv.x + bv.x, o1 = (v.y-mu)*rs*wv.y + bv.y;
    float o2 = (v.z-mu)*rs*wv.z + bv.z, o3 = (v.w-mu)*rs*wv.w + bv.w;
    bf16 h0,h1,h2,h3,l0,l1,l2,l3;
    bfsplit(o0,h0,l0); bfsplit(o1,h1,l1); bfsplit(o2,h2,l2); bfsplit(o3,h3,l3);
    size_t oi = ((size_t)row*1024 + t*4) >> 1;
    bf162 pa, pb;
    pa.x=h0;pa.y=h1;pb.x=h2;pb.y=h3; ((bf162*)yh)[oi]=pa; ((bf162*)yh)[oi+1]=pb;
    pa.x=l0;pa.y=l1;pb.x=l2;pb.y=l3; ((bf162*)yl)[oi]=pa; ((bf162*)yl)[oi+1]=pb;
}

// ---------- HMMA GEMM: 128x256 CTA tile, 512 thr, bf16x3 -> fp32 ----------
// stage layout: Ah[128x80B] Al[128x80B] Bh[256x80B] Bl[256x80B] = 61440 B
#define ATILE_B  10240
#define BTILE_B  20480
#define STAGE_B  61440
#define GSMEM    (3*STAGE_B)

__device__ __forceinline__ void issue_stage(
    const bf16* __restrict__ Ah, const bf16* __restrict__ Al,
    const bf16* __restrict__ Bh, const bf16* __restrict__ Bl,
    uint32_t sbase, int bm, int bn, int ko, int K, int tid)
{
    #pragma unroll
    for (int i = 0; i < 2; ++i) {      // A: 1024 chunks
        int lin = tid + (i << 9);
        int tile = lin >> 9;           // 0: Ah, 1: Al
        int wit = lin & 511;
        int r = wit >> 2, ch = wit & 3;
        const bf16* gp = (tile ? Al : Ah) + (size_t)(bm + r) * K + ko + ch*8;
        CP_ASYNC16(sbase + tile*ATILE_B + r*80 + ch*16, gp);
    }
    #pragma unroll
    for (int i = 0; i < 4; ++i) {      // B: 2048 chunks
        int lin = tid + (i << 9);
        int hb = lin >> 10;            // 0: Bh, 1: Bl
        int wit = lin & 1023;
        int r = wit >> 2, ch = wit & 3;
        const bf16* gp = (hb ? Bl : Bh) + (size_t)(bn + r) * K + ko + ch*8;
        CP_ASYNC16(sbase + 2*ATILE_B + hb*BTILE_B + r*80 + ch*16, gp);
    }
    CP_COMMIT();
}

// EPI 0: QKV scatter(+bias) q/k->bf16 hi/lo, v->f32 | 1: +bias+res->outf
// EPI 2: bfsplit(relu(acc+b)*(m>.5)) | 3: res+(acc+b)*(m>.5)
template<int EPI>
__global__ void __launch_bounds__(512)
tc_gemm(const bf16* __restrict__ Ah, const bf16* __restrict__ Al,
        const bf16* __restrict__ Bh, const bf16* __restrict__ Bl,
        const float* __restrict__ bias, const float* __restrict__ aux,
        const float* __restrict__ res, float* __restrict__ outf,
        bf16* __restrict__ outh, bf16* __restrict__ outl, int N, int K)
{
    extern __shared__ char smem[];
    uint32_t sb = s2u(smem);
    const int tid = threadIdx.x, lane = tid & 31, wid = tid >> 5;
    const int wm = wid & 3, wn = wid >> 2;
    const int bm = blockIdx.y << 7, bn = blockIdx.x << 8;

    float acc[2][8][4];
    #pragma unroll
    for (int i = 0; i < 2; ++i)
        #pragma unroll
        for (int j = 0; j < 8; ++j)
            #pragma unroll
            for (int q = 0; q < 4; ++q) acc[i][j][q] = 0.f;

    const int ktn = K >> 5;
    issue_stage(Ah, Al, Bh, Bl, sb,           bm, bn, 0,  K, tid);
    issue_stage(Ah, Al, Bh, Bl, sb + STAGE_B, bm, bn, 32, K, tid);

    const int a_ro = (lane & 15);
    const int a_ko = (lane >> 4) * 8;
    const int b_rp = ((lane >> 4) & 1) * 8 + (lane & 7);
    const int b_ko = ((lane >> 3) & 1) * 8;

    for (int kt = 0; kt < ktn; ++kt) {
        if (kt + 1 < ktn) asm volatile("cp.async.wait_group 1;" ::: "memory");
        else              asm volatile("cp.async.wait_group 0;" ::: "memory");
        __syncthreads();
        if (kt + 2 < ktn)
            issue_stage(Ah, Al, Bh, Bl, sb + ((kt + 2) % 3) * STAGE_B,
                        bm, bn, (kt + 2) * 32, K, tid);

        uint32_t st = sb + (kt % 3) * STAGE_B;
        #pragma unroll
        for (int ks = 0; ks < 2; ++ks) {
            uint32_t ahi[2][4], alo[2][4];
            #pragma unroll
            for (int mf = 0; mf < 2; ++mf) {
                uint32_t ad = st + (wm*32 + mf*16 + a_ro)*80 + (ks*16 + a_ko)*2;
                ldsm4(ahi[mf], ad);
                ldsm4(alo[mf], ad + ATILE_B);
            }
            #pragma unroll
            for (int np = 0; np < 4; ++np) {
                uint32_t bd = st + 2*ATILE_B + (wn*64 + np*16 + b_rp)*80 + (ks*16 + b_ko)*2;
                uint32_t bhi[4], blo[4];
                ldsm4(bhi, bd);
                ldsm4(blo, bd + BTILE_B);
                #pragma unroll
                for (int mf = 0; mf < 2; ++mf)
                    #pragma unroll
                    for (int ns = 0; ns < 0; ++ns) {}
                #pragma unroll
                for (int mf = 0; mf < 2; ++mf) {
                    mma16816(acc[mf][np*2  ], ahi[mf], &bhi[0]);
                    mma16816(acc[mf][np*2+1], ahi[mf], &bhi[2]);
                }
                #pragma unroll
                for (int mf = 0; mf < 2; ++mf) {
                    mma16816(acc[mf][np*2  ], ahi[mf], &blo[0]);
                    mma16816(acc[mf][np*2+1], ahi[mf], &blo[2]);
                }
                #pragma unroll
                for (int mf = 0; mf < 2; ++mf) {
                    mma16816(acc[mf][np*2  ], alo[mf], &bhi[0]);
                    mma16816(acc[mf][np*2+1], alo[mf], &bhi[2]);
                }
            }
        }
        __syncthreads();
    }

    const int tr = lane >> 2;
    const int tc = (lane & 3) * 2;
    #pragma unroll
    for (int mf = 0; mf < 2; ++mf) {
        #pragma unroll
        for (int nf = 0; nf < 8; ++nf) {
            int gj = bn + wn*64 + nf*8 + tc;
            float2 b2 = *(const float2*)&bias[gj];
            #pragma unroll
            for (int h = 0; h < 2; ++h) {
                int gi = bm + wm*32 + mf*16 + tr + h*8;
                float v0 = acc[mf][nf][h*2]   + b2.x;
                float v1 = acc[mf][nf][h*2+1] + b2.y;
                size_t off = (size_t)gi * N + gj;
                if (EPI == 0) {
                    int wh = gj >> 10, hh = (gj >> 6) & 15, d = gj & 63;
                    int bb = gi >> 10, nn = gi & 1023;
                    size_t idx = (((size_t)(bb*16 + hh))*1024 + nn)*64 + d;
                    if (wh == 2) {
                        float2 o; o.x = v0; o.y = v1;
                        *(float2*)&g_v[idx] = o;
                    } else {
                        bf16 h0,l0,h1,l1;
                        bfsplit(v0,h0,l0); bfsplit(v1,h1,l1);
                        bf162 ph, pl; ph.x=h0; ph.y=h1; pl.x=l0; pl.y=l1;
                        if (wh == 0) { *(bf162*)&g_qh[idx]=ph; *(bf162*)&g_ql[idx]=pl; }
                        else         { *(bf162*)&g_kh[idx]=ph; *(bf162*)&g_kl[idx]=pl; }
                    }
                } else if (EPI == 1) {
                    float2 rr = *(const float2*)&res[off];
                    float2 o; o.x = v0 + rr.x; o.y = v1 + rr.y;
                    *(float2*)&outf[off] = o;
                } else if (EPI == 2) {
                    float2 m = *(const float2*)&aux[off];
                    v0 = (m.x > 0.5f) ? fmaxf(v0, 0.f) : 0.f;
                    v1 = (m.y > 0.5f) ? fmaxf(v1, 0.f) : 0.f;
                    bf16 h0,l0,h1,l1;
                    bfsplit(v0,h0,l0); bfsplit(v1,h1,l1);
                    bf162 p; p.x=h0; p.y=h1; *(bf162*)&outh[off] = p;
                    p.x=l0; p.y=l1;          *(bf162*)&outl[off] = p;
                } else {
                    float2 m  = *(const float2*)&aux[off];
                    float2 rr = *(const float2*)&res[off];
                    float2 o;
                    o.x = rr.x + ((m.x > 0.5f) ? v0 : 0.f);
                    o.y = rr.y + ((m.y > 0.5f) ? v1 : 0.f);
                    *(float2*)&outf[off] = o;
                }
            }
        }
    }
}

// ---------------- sparse attention: HMMA scores + scalar sparse PV --------
#define SS_STR  1034
#define ATTN_SMEM (46080 + 32*SS_STR*4)

__global__ void __launch_bounds__(512)
attn_kernel()
{
    extern __shared__ char smraw[];
    float* smf = (float*)smraw;
    uint32_t sb = s2u(smraw);

    int blk = blockIdx.x, bh = blk >> 5, n0 = (blk & 31) << 5;
    int tid = threadIdx.x, lane = tid & 31, w = tid >> 5;
    const size_t bhoff = (size_t)bh * 65536;

    {
        int tile = tid >> 8, wit = tid & 255, r = wit >> 3, ch = wit & 7;
        const bf16* gsrc = (tile ? g_ql : g_qh) + bhoff + (size_t)(n0 + r)*64 + ch*8;
        *(uint4*)(smraw + tile*4608 + r*144 + ch*16) = *(const uint4*)gsrc;
    }
    __syncthreads();

    const int wm = w & 1, wn = w >> 1;
    const int a_ro = lane & 15, a_ko = (lane >> 4) * 8;
    const int b_rp = ((lane >> 4) & 1) * 8 + (lane & 7);
    const int b_ko = ((lane >> 3) & 1) * 8;
    uint32_t qhi[4][4], qlo[4][4];
    #pragma unroll
    for (int ks = 0; ks < 4; ++ks) {
        uint32_t qa = sb + (wm*16 + a_ro)*144 + (ks*16 + a_ko)*2;
        ldsm4(qhi[ks], qa);
        ldsm4(qlo[ks], qa + 4608);
    }
    const int tr = lane >> 2, tc = (lane & 3) * 2;

    for (int kt = 0; kt < 8; ++kt) {
        __syncthreads();
        #pragma unroll
        for (int i = 0; i < 4; ++i) {
            int lin = tid + (i << 9);
            int tile = (lin >> 10) & 1, wit = lin & 1023;
            int r = wit >> 3, ch = wit & 7;
            const bf16* gsrc = (tile ? g_kl : g_kh) + bhoff + (size_t)(kt*128 + r)*64 + ch*8;
            *(uint4*)(smraw + 9216 + tile*18432 + r*144 + ch*16) = *(const uint4*)gsrc;
        }
        __syncthreads();
        float acc[2][4];
        #pragma unroll
        for (int nf = 0; nf < 2; ++nf)
            #pragma unroll
            for (int q = 0; q < 4; ++q) acc[nf][q] = 0.f;
        #pragma unroll
        for (int ks = 0; ks < 4; ++ks) {
            uint32_t bd = sb + 9216 + (wn*16 + b_rp)*144 + (ks*16 + b_ko)*2;
            uint32_t bhi[4], blo[4];
            ldsm4(bhi, bd);
            ldsm4(blo, bd + 18432);
            mma16816(acc[0], qhi[ks], &bhi[0]);
            mma16816(acc[1], qhi[ks], &bhi[2]);
            mma16816(acc[0], qhi[ks], &blo[0]);
            mma16816(acc[1], qhi[ks], &blo[2]);
            mma16816(acc[0], qlo[ks], &bhi[0]);
            mma16816(acc[1], qlo[ks], &bhi[2]);
        }
        #pragma unroll
        for (int nf = 0; nf < 2; ++nf) {
            int key = kt*128 + wn*16 + nf*8 + tc;
            int row0 = wm*16 + tr;
            float2 o;
            o.x = acc[nf][0]*0.125f; o.y = acc[nf][1]*0.125f;
            *(float2*)&smf[11520 + row0*SS_STR + key] = o;
            o.x = acc[nf][2]*0.125f; o.y = acc[nf][3]*0.125f;
            *(float2*)&smf[11520 + (row0+8)*SS_STR + key] = o;
        }
    }
    __syncthreads();

    int r0 = 2 * w;
    #pragma unroll 1
    for (int rr = 0; rr < 2; ++rr) {
        float* srow = &smf[11520 + (r0 + rr) * SS_STR];
        unsigned key[32];
        float lmax = -3.4e38f;
        #pragma unroll
        for (int i = 0; i < 32; ++i) {
            float s = srow[lane + 32*i];
            lmax = fmaxf(lmax, s);
            unsigned ub = __float_as_uint(s);
            key[i] = ub ^ (((unsigned)((int)ub >> 31)) | 0x80000000u);
        }
        #pragma unroll
        for (int o = 16; o; o >>= 1) lmax = fmaxf(lmax, __shfl_xor_sync(~0u, lmax, o));
        unsigned lo = 0u, hi = 0xFFFFFFFFu;
        while (lo < hi) {
            unsigned mid = lo + (unsigned)(((unsigned long long)(hi - lo) + 1ull) >> 1);
            unsigned c = 0;
            #pragma unroll
            for (int i = 0; i < 32; ++i) c += (key[i] >= mid) ? 1u : 0u;
            c = __reduce_add_sync(~0u, c);
            if (c >= (unsigned)KSP) lo = mid; else hi = mid - 1u;
        }
        unsigned T = lo;
        float lsum = 0.f;
        #pragma unroll
        for (int i = 0; i < 32; ++i) {
            float e = 0.f;
            if (key[i] >= T) {
                unsigned ub = key[i];
                unsigned fb = ub ^ ((ub & 0x80000000u) ? 0x80000000u : 0xFFFFFFFFu);
                e = __expf(__uint_as_float(fb) - lmax);
            }
            lsum += e;
            srow[lane + 32*i] = e;
        }
        #pragma unroll
        for (int o = 16; o; o >>= 1) lsum += __shfl_xor_sync(~0u, lsum, o);
        float inv = 1.f / lsum;
        #pragma unroll
        for (int i = 0; i < 32; ++i) srow[lane + 32*i] *= inv;
    }

    float* sV = smf + 2304;
    float o00=0, o01=0, o10=0, o11=0;
    for (int kt = 0; kt < 8; ++kt) {
        __syncthreads();
        #pragma unroll
        for (int i = 0; i < 4; ++i) {
            int lin = tid + (i << 9);
            int ky = lin >> 4, c = lin & 15;
            float4 vv = *(const float4*)&g_v[bhoff + (size_t)(kt*128 + ky)*64 + c*4];
            *(float4*)&sV[ky*68 + c*4] = vv;
        }
        __syncthreads();
        const float* pa = &smf[11520 + r0*SS_STR + kt*128];
        const float* pb = pa + SS_STR;
        #pragma unroll 4
        for (int m = 0; m < 128; ++m) {
            float x0 = pa[m];
            if (x0 != 0.f) {
                o00 = fmaf(x0, sV[m*68 + lane     ], o00);
                o01 = fmaf(x0, sV[m*68 + lane + 32], o01);
            }
            float x1 = pb[m];
            if (x1 != 0.f) {
                o10 = fmaf(x1, sV[m*68 + lane     ], o10);
                o11 = fmaf(x1, sV[m*68 + lane + 32], o11);
            }
        }
    }
    int bb = bh >> 4, hh = bh & 15;
    #pragma unroll
    for (int rr = 0; rr < 2; ++rr) {
        size_t base = ((size_t)(bb*1024 + n0 + r0 + rr)) * 1024 + hh*64;
        bf16 h, l;
        bfsplit(rr ? o10 : o00, h, l);
        g_ath[base + lane] = h; g_atl[base + lane] = l;
        bfsplit(rr ? o11 : o01, h, l);
        g_ath[base + lane + 32] = h; g_atl[base + lane + 32] = l;
    }
}

// ---------------- launch ----------------
extern "C" void kernel_launch(void* const* d_in, const int* in_sizes, int n_in,
                              void* d_out, int out_size)
{
    (void)in_sizes; (void)n_in; (void)out_size;
    const float* x     = (const float*)d_in[0];
    const float* ln1_w = (const float*)d_in[1];
    const float* ln1_b = (const float*)d_in[2];
    const float* qkv_w = (const float*)d_in[3];
    const float* qkv_b = (const float*)d_in[4];
    const float* out_w = (const float*)d_in[5];
    const float* out_b = (const float*)d_in[6];
    const float* ln2_w = (const float*)d_in[7];
    const float* ln2_b = (const float*)d_in[8];
    const float* w1    = (const float*)d_in[9];
    const float* b1    = (const float*)d_in[10];
    const float* w2    = (const float*)d_in[11];
    const float* b2    = (const float*)d_in[12];
    const float* mask1 = (const float*)d_in[13];
    const float* mask2 = (const float*)d_in[14];
    float* out = (float*)d_out;

    void *x1, *xnh, *xnl, *hnh, *hnl, *ath, *atl, *h1h, *h1l,
         *qwh, *qwl, *owh, *owl, *w1h, *w1l, *w2h, *w2l;
    cudaGetSymbolAddress(&x1, g_x1);
    cudaGetSymbolAddress(&xnh, g_xnh); cudaGetSymbolAddress(&xnl, g_xnl);
    cudaGetSymbolAddress(&hnh, g_hnh); cudaGetSymbolAddress(&hnl, g_hnl);
    cudaGetSymbolAddress(&ath, g_ath); cudaGetSymbolAddress(&atl, g_atl);
    cudaGetSymbolAddress(&h1h, g_h1h); cudaGetSymbolAddress(&h1l, g_h1l);
    cudaGetSymbolAddress(&qwh, g_qwh); cudaGetSymbolAddress(&qwl, g_qwl);
    cudaGetSymbolAddress(&owh, g_owh); cudaGetSymbolAddress(&owl, g_owl);
    cudaGetSymbolAddress(&w1h, g_w1h); cudaGetSymbolAddress(&w1l, g_w1l);
    cudaGetSymbolAddress(&w2h, g_w2h); cudaGetSymbolAddress(&w2l, g_w2l);

    cudaFuncSetAttribute(attn_kernel, cudaFuncAttributeMaxDynamicSharedMemorySize, ATTN_SMEM);
    cudaFuncSetAttribute(tc_gemm<0>, cudaFuncAttributeMaxDynamicSharedMemorySize, GSMEM);
    cudaFuncSetAttribute(tc_gemm<1>, cudaFuncAttributeMaxDynamicSharedMemorySize, GSMEM);
    cudaFuncSetAttribute(tc_gemm<2>, cudaFuncAttributeMaxDynamicSharedMemorySize, GSMEM);
    cudaFuncSetAttribute(tc_gemm<3>, cudaFuncAttributeMaxDynamicSharedMemorySize, GSMEM);

    // launch order matters for ncu -s 5: [0]cvt [1]cvt [2]ln1 [3]gemm0 [4]attn [5]gemm1
    cvt_split2<<<4096, 256>>>(qkv_w, (bf16*)qwh, (bf16*)qwl, 786432,
                              out_w, (bf16*)owh, (bf16*)owl, 262144);
    cvt_split2<<<8192, 256>>>(w1, (bf16*)w1h, (bf16*)w1l, 1048576,
                              w2, (bf16*)w2h, (bf16*)w2l, 1048576);

    ln_bf16<<<M_, 256>>>(x, ln1_w, ln1_b, (bf16*)xnh, (bf16*)xnl);

    tc_gemm<0><<<dim3(12, 64), 512, GSMEM>>>((bf16*)xnh, (bf16*)xnl,
        (bf16*)qwh, (bf16*)qwl, qkv_b, nullptr, nullptr, nullptr, nullptr, nullptr,
        3*C_, C_);

    attn_kernel<<<BH_*(N_/32), 512, ATTN_SMEM>>>();

    tc_gemm<1><<<dim3(4, 64), 512, GSMEM>>>((bf16*)ath, (bf16*)atl,
        (bf16*)owh, (bf16*)owl, out_b, nullptr, x, (float*)x1, nullptr, nullptr,
        C_, C_);

    ln_bf16<<<M_, 256>>>((float*)x1, ln2_w, ln2_b, (bf16*)hnh, (bf16*)hnl);

    tc_gemm<2><<<dim3(16, 64), 512, GSMEM>>>((bf16*)hnh, (bf16*)hnl,
        (bf16*)w1h, (bf16*)w1l, b1, mask1, nullptr, nullptr, (bf16*)h1h, (bf16*)h1l,
        FF_, C_);

    tc_gemm<3><<<dim3(4, 64), 512, GSMEM>>>((bf16*)h1h, (bf16*)h1l,
        (bf16*)w2h, (bf16*)w2l, b2, mask2, (float*)x1, out, nullptr, nullptr,
        C_, FF_);
}

// round 7
// speedup vs baseline: 2.0653x; 1.0723x over previous
#include <cuda_runtime.h>
#include <cuda_bf16.h>
#include <stdint.h>

#define B_   8
#define N_   1024
#define C_   1024
#define HD_  64
#define FF_  4096
#define BH_  128
#define M_   8192
#define KSP  102

typedef __nv_bfloat16 bf16;
typedef __nv_bfloat162 bf162;

// ---------------- scratch ----------------
__device__ __align__(256) float g_v[(size_t)BH_*N_*HD_];
__device__ __align__(256) float g_x1[(size_t)M_*C_];
__device__ __align__(256) bf16 g_qh[(size_t)BH_*N_*HD_], g_ql[(size_t)BH_*N_*HD_];
__device__ __align__(256) bf16 g_kh[(size_t)BH_*N_*HD_], g_kl[(size_t)BH_*N_*HD_];
__device__ __align__(256) bf16 g_xnh[(size_t)M_*C_],  g_xnl[(size_t)M_*C_];
__device__ __align__(256) bf16 g_hnh[(size_t)M_*C_],  g_hnl[(size_t)M_*C_];
__device__ __align__(256) bf16 g_ath[(size_t)M_*C_],  g_atl[(size_t)M_*C_];
__device__ __align__(256) bf16 g_h1h[(size_t)M_*FF_], g_h1l[(size_t)M_*FF_];
__device__ __align__(256) bf16 g_qwh[(size_t)3*C_*C_], g_qwl[(size_t)3*C_*C_];
__device__ __align__(256) bf16 g_owh[(size_t)C_*C_],   g_owl[(size_t)C_*C_];
__device__ __align__(256) bf16 g_w1h[(size_t)FF_*C_],  g_w1l[(size_t)FF_*C_];
__device__ __align__(256) bf16 g_w2h[(size_t)C_*FF_],  g_w2l[(size_t)C_*FF_];

// ---------------- helpers ----------------
__device__ __forceinline__ uint32_t s2u(const void* p) {
    uint32_t a;
    asm("{ .reg .u64 t; cvta.to.shared.u64 t, %1; cvt.u32.u64 %0, t; }" : "=r"(a) : "l"(p));
    return a;
}
__device__ __forceinline__ void bfsplit(float v, bf16& h, bf16& l) {
    h = __float2bfloat16(v);
    l = __float2bfloat16(v - __bfloat162float(h));
}
__device__ __forceinline__ void ldsm4(uint32_t* r, uint32_t a) {
    asm volatile("ldmatrix.sync.aligned.m8n8.x4.shared.b16 {%0,%1,%2,%3}, [%4];"
        : "=r"(r[0]), "=r"(r[1]), "=r"(r[2]), "=r"(r[3]) : "r"(a));
}
__device__ __forceinline__ void mma16816(float* c, const uint32_t* a, const uint32_t* b) {
    asm volatile("mma.sync.aligned.m16n8k16.row.col.f32.bf16.bf16.f32 "
        "{%0,%1,%2,%3}, {%4,%5,%6,%7}, {%8,%9}, {%0,%1,%2,%3};"
        : "+f"(c[0]), "+f"(c[1]), "+f"(c[2]), "+f"(c[3])
        : "r"(a[0]), "r"(a[1]), "r"(a[2]), "r"(a[3]), "r"(b[0]), "r"(b[1]));
}
#define CP_ASYNC16(s, g) \
    asm volatile("cp.async.cg.shared.global [%0], [%1], 16;" :: "r"(s), "l"(g))
#define CP_COMMIT() asm volatile("cp.async.commit_group;" ::: "memory")
#define CP_WAIT0()  asm volatile("cp.async.wait_group 0;" ::: "memory")

// ---------------- weight split ----------------
__global__ void __launch_bounds__(256)
cvt_split2(const float* __restrict__ s0, bf16* __restrict__ h0, bf16* __restrict__ l0, int n0,
           const float* __restrict__ s1, bf16* __restrict__ h1, bf16* __restrict__ l1, int n1)
{
    int i = blockIdx.x * 256 + threadIdx.x;
    const float* s; bf16 *h, *l;
    if (i < n0) { s = s0; h = h0; l = l0; }
    else { i -= n0; if (i >= n1) return; s = s1; h = h1; l = l1; }
    float4 v = ((const float4*)s)[i];
    bf16 h0_,h1_,h2_,h3_,l0_,l1_,l2_,l3_;
    bfsplit(v.x,h0_,l0_); bfsplit(v.y,h1_,l1_); bfsplit(v.z,h2_,l2_); bfsplit(v.w,h3_,l3_);
    bf162 a,b;
    a.x=h0_;a.y=h1_;b.x=h2_;b.y=h3_; ((bf162*)h)[i*2]=a; ((bf162*)h)[i*2+1]=b;
    a.x=l0_;a.y=l1_;b.x=l2_;b.y=l3_; ((bf162*)l)[i*2]=a; ((bf162*)l)[i*2+1]=b;
}

// ---------------- LayerNorm -> bf16 hi/lo ----------------
__global__ void __launch_bounds__(256)
ln_bf16(const float* __restrict__ x, const float* __restrict__ w,
        const float* __restrict__ b, bf16* __restrict__ yh, bf16* __restrict__ yl)
{
    __shared__ float red[16];
    int row = blockIdx.x, t = threadIdx.x;
    float4 v = ((const float4*)(x + (size_t)row * 1024))[t];
    float s  = v.x + v.y + v.z + v.w;
    float ss = v.x*v.x + v.y*v.y + v.z*v.z + v.w*v.w;
    #pragma unroll
    for (int o = 16; o; o >>= 1) {
        s  += __shfl_xor_sync(~0u, s, o);
        ss += __shfl_xor_sync(~0u, ss, o);
    }
    if ((t & 31) == 0) { red[t>>5] = s; red[(t>>5)+8] = ss; }
    __syncthreads();
    if (t == 0) {
        float ts=0.f, tss=0.f;
        #pragma unroll
        for (int i = 0; i < 8; ++i) { ts += red[i]; tss += red[i+8]; }
        float mu = ts * (1.f/1024.f);
        red[0] = mu; red[1] = rsqrtf(tss*(1.f/1024.f) - mu*mu + 1e-5f);
    }
    __syncthreads();
    float mu = red[0], rs = red[1];
    float4 wv = ((const float4*)w)[t];
    float4 bv = ((const float4*)b)[t];
    float o0 = (v.x-mu)*rs*wv.x + bv.x, o1 = (v.y-mu)*rs*wv.y + bv.y;
    float o2 = (v.z-mu)*rs*wv.z + bv.z, o3 = (v.w-mu)*rs*wv.w + bv.w;
    bf16 h0,h1,h2,h3,l0,l1,l2,l3;
    bfsplit(o0,h0,l0); bfsplit(o1,h1,l1); bfsplit(o2,h2,l2); bfsplit(o3,h3,l3);
    size_t oi = ((size_t)row*1024 + t*4) >> 1;
    bf162 pa, pb;
    pa.x=h0;pa.y=h1;pb.x=h2;pb.y=h3; ((bf162*)yh)[oi]=pa; ((bf162*)yh)[oi+1]=pb;
    pa.x=l0;pa.y=l1;pb.x=l2;pb.y=l3; ((bf162*)yl)[oi]=pa; ((bf162*)yl)[oi+1]=pb;
}

// ---- HMMA GEMM: 128x128 tile, 256 thr, 2-stage, 2 CTAs/SM, bf16x3 ----
#define ATILE_B  10240
#define STAGE_B  40960
#define GSMEM    (2*STAGE_B)

__device__ __forceinline__ void issue_stage(
    const bf16* __restrict__ Ah, const bf16* __restrict__ Al,
    const bf16* __restrict__ Bh, const bf16* __restrict__ Bl,
    uint32_t sbase, int bm, int bn, int ko, int K, int tid)
{
    #pragma unroll
    for (int i = 0; i < 8; ++i) {
        int lin = tid + (i << 8);
        int tile = lin >> 9;
        int wit = lin & 511;
        int r = wit >> 2, ch = wit & 3;
        const bf16* gp;
        if      (tile == 0) gp = Ah + (size_t)(bm + r) * K + ko + ch*8;
        else if (tile == 1) gp = Al + (size_t)(bm + r) * K + ko + ch*8;
        else if (tile == 2) gp = Bh + (size_t)(bn + r) * K + ko + ch*8;
        else                gp = Bl + (size_t)(bn + r) * K + ko + ch*8;
        CP_ASYNC16(sbase + tile*ATILE_B + r*80 + ch*16, gp);
    }
    CP_COMMIT();
}

template<int EPI>
__global__ void __launch_bounds__(256, 2)
tc_gemm(const bf16* __restrict__ Ah, const bf16* __restrict__ Al,
        const bf16* __restrict__ Bh, const bf16* __restrict__ Bl,
        const float* __restrict__ bias, const float* __restrict__ aux,
        const float* __restrict__ res, float* __restrict__ outf,
        bf16* __restrict__ outh, bf16* __restrict__ outl, int N, int K)
{
    extern __shared__ char smem[];
    uint32_t sb = s2u(smem);
    const int tid = threadIdx.x, lane = tid & 31, wid = tid >> 5;
    const int wm = wid & 3, wn = wid >> 2;
    const int bm = blockIdx.y << 7, bn = blockIdx.x << 7;

    float acc[2][8][4];
    #pragma unroll
    for (int i = 0; i < 2; ++i)
        #pragma unroll
        for (int j = 0; j < 8; ++j)
            #pragma unroll
            for (int q = 0; q < 4; ++q) acc[i][j][q] = 0.f;

    const int ktn = K >> 5;
    issue_stage(Ah, Al, Bh, Bl, sb, bm, bn, 0, K, tid);

    const int a_ro = (lane & 15);
    const int a_ko = (lane >> 4) * 8;
    const int b_rp = ((lane >> 4) & 1) * 8 + (lane & 7);
    const int b_ko = ((lane >> 3) & 1) * 8;

    for (int kt = 0; kt < ktn; ++kt) {
        CP_WAIT0();
        __syncthreads();
        if (kt + 1 < ktn)
            issue_stage(Ah, Al, Bh, Bl, sb + ((kt + 1) & 1) * STAGE_B,
                        bm, bn, (kt + 1) * 32, K, tid);
        uint32_t st = sb + (kt & 1) * STAGE_B;
        #pragma unroll
        for (int ks = 0; ks < 2; ++ks) {
            uint32_t ahi[2][4], alo[2][4];
            #pragma unroll
            for (int mf = 0; mf < 2; ++mf) {
                uint32_t ad = st + (wm*32 + mf*16 + a_ro)*80 + (ks*16 + a_ko)*2;
                ldsm4(ahi[mf], ad);
                ldsm4(alo[mf], ad + ATILE_B);
            }
            #pragma unroll
            for (int np = 0; np < 4; ++np) {
                uint32_t bd = st + 2*ATILE_B + (wn*64 + np*16 + b_rp)*80 + (ks*16 + b_ko)*2;
                uint32_t bhi[4], blo[4];
                ldsm4(bhi, bd);
                ldsm4(blo, bd + ATILE_B);
                #pragma unroll
                for (int mf = 0; mf < 2; ++mf) {
                    mma16816(acc[mf][np*2  ], ahi[mf], &bhi[0]);
                    mma16816(acc[mf][np*2+1], ahi[mf], &bhi[2]);
                }
                #pragma unroll
                for (int mf = 0; mf < 2; ++mf) {
                    mma16816(acc[mf][np*2  ], ahi[mf], &blo[0]);
                    mma16816(acc[mf][np*2+1], ahi[mf], &blo[2]);
                }
                #pragma unroll
                for (int mf = 0; mf < 2; ++mf) {
                    mma16816(acc[mf][np*2  ], alo[mf], &bhi[0]);
                    mma16816(acc[mf][np*2+1], alo[mf], &bhi[2]);
                }
            }
        }
    }

    const int tr = lane >> 2;
    const int tc = (lane & 3) * 2;
    #pragma unroll
    for (int mf = 0; mf < 2; ++mf) {
        #pragma unroll
        for (int nf = 0; nf < 8; ++nf) {
            int gj = bn + wn*64 + nf*8 + tc;
            float2 b2 = *(const float2*)&bias[gj];
            #pragma unroll
            for (int h = 0; h < 2; ++h) {
                int gi = bm + wm*32 + mf*16 + tr + h*8;
                float v0 = acc[mf][nf][h*2]   + b2.x;
                float v1 = acc[mf][nf][h*2+1] + b2.y;
                size_t off = (size_t)gi * N + gj;
                if (EPI == 0) {
                    int wh = gj >> 10, hh = (gj >> 6) & 15, d = gj & 63;
                    int bb = gi >> 10, nn = gi & 1023;
                    size_t idx = (((size_t)(bb*16 + hh))*1024 + nn)*64 + d;
                    if (wh == 2) {
                        float2 o; o.x = v0; o.y = v1;
                        *(float2*)&g_v[idx] = o;
                    } else {
                        bf16 h0,l0,h1,l1;
                        bfsplit(v0,h0,l0); bfsplit(v1,h1,l1);
                        bf162 ph, pl; ph.x=h0; ph.y=h1; pl.x=l0; pl.y=l1;
                        if (wh == 0) { *(bf162*)&g_qh[idx]=ph; *(bf162*)&g_ql[idx]=pl; }
                        else         { *(bf162*)&g_kh[idx]=ph; *(bf162*)&g_kl[idx]=pl; }
                    }
                } else if (EPI == 1) {
                    float2 rr = *(const float2*)&res[off];
                    float2 o; o.x = v0 + rr.x; o.y = v1 + rr.y;
                    *(float2*)&outf[off] = o;
                } else if (EPI == 2) {
                    float2 m = *(const float2*)&aux[off];
                    v0 = (m.x > 0.5f) ? fmaxf(v0, 0.f) : 0.f;
                    v1 = (m.y > 0.5f) ? fmaxf(v1, 0.f) : 0.f;
                    bf16 h0,l0,h1,l1;
                    bfsplit(v0,h0,l0); bfsplit(v1,h1,l1);
                    bf162 p; p.x=h0; p.y=h1; *(bf162*)&outh[off] = p;
                    p.x=l0; p.y=l1;          *(bf162*)&outl[off] = p;
                } else {
                    float2 m  = *(const float2*)&aux[off];
                    float2 rr = *(const float2*)&res[off];
                    float2 o;
                    o.x = rr.x + ((m.x > 0.5f) ? v0 : 0.f);
                    o.y = rr.y + ((m.y > 0.5f) ? v1 : 0.f);
                    *(float2*)&outf[off] = o;
                }
            }
        }
    }
}

// ------- sparse attention: cp.async double-buffered K/V, HMMA scores -------
// smem: Q hi/lo 9216 | K bufs 2x36864 (V reuses: 2x34816) | sS 32x1034 f32
#define SS_STR  1034
#define SS_OFF  20736              /* (9216+73728)/4 */
#define ATTN_SMEM (9216 + 73728 + 32*SS_STR*4)

__device__ __forceinline__ void issue_k(uint32_t sb, size_t bhoff, int kt, int buf, int tid) {
    #pragma unroll
    for (int i = 0; i < 4; ++i) {
        int lin = tid + (i << 9);
        int tile = lin >> 10, wit = lin & 1023;
        int r = wit >> 3, ch = wit & 7;
        const bf16* gsrc = (tile ? g_kl : g_kh) + bhoff + (size_t)(kt*128 + r)*64 + ch*8;
        CP_ASYNC16(sb + 9216 + buf*36864 + tile*18432 + r*144 + ch*16, gsrc);
    }
    CP_COMMIT();
}
__device__ __forceinline__ void issue_v(uint32_t sb, size_t bhoff, int kt, int buf, int tid) {
    #pragma unroll
    for (int i = 0; i < 4; ++i) {
        int lin = tid + (i << 9);
        int r = lin >> 4, ch = lin & 15;
        const float* gsrc = &g_v[bhoff + (size_t)(kt*128 + r)*64 + ch*4];
        CP_ASYNC16(sb + 9216 + buf*34816 + r*272 + ch*16, gsrc);
    }
    CP_COMMIT();
}

__global__ void __launch_bounds__(512)
attn_kernel()
{
    extern __shared__ char smraw[];
    float* smf = (float*)smraw;
    uint32_t sb = s2u(smraw);

    int blk = blockIdx.x, bh = blk >> 5, n0 = (blk & 31) << 5;
    int tid = threadIdx.x, lane = tid & 31, w = tid >> 5;
    const size_t bhoff = (size_t)bh * 65536;

    {
        int tile = tid >> 8, wit = tid & 255, r = wit >> 3, ch = wit & 7;
        const bf16* gsrc = (tile ? g_ql : g_qh) + bhoff + (size_t)(n0 + r)*64 + ch*8;
        *(uint4*)(smraw + tile*4608 + r*144 + ch*16) = *(const uint4*)gsrc;
    }
    issue_k(sb, bhoff, 0, 0, tid);
    __syncthreads();

    const int wm = w & 1, wn = w >> 1;
    const int a_ro = lane & 15, a_ko = (lane >> 4) * 8;
    const int b_rp = ((lane >> 4) & 1) * 8 + (lane & 7);
    const int b_ko = ((lane >> 3) & 1) * 8;
    uint32_t qhi[4][4], qlo[4][4];
    #pragma unroll
    for (int ks = 0; ks < 4; ++ks) {
        uint32_t qa = sb + (wm*16 + a_ro)*144 + (ks*16 + a_ko)*2;
        ldsm4(qhi[ks], qa);
        ldsm4(qlo[ks], qa + 4608);
    }
    const int tr = lane >> 2, tc = (lane & 3) * 2;

    // ---- phase 1: scores ----
    for (int kt = 0; kt < 8; ++kt) {
        CP_WAIT0();
        __syncthreads();
        if (kt < 7) issue_k(sb, bhoff, kt + 1, (kt + 1) & 1, tid);
        uint32_t kb = sb + 9216 + (kt & 1)*36864;
        float acc[2][4];
        #pragma unroll
        for (int nf = 0; nf < 2; ++nf)
            #pragma unroll
            for (int q = 0; q < 4; ++q) acc[nf][q] = 0.f;
        #pragma unroll
        for (int ks = 0; ks < 4; ++ks) {
            uint32_t bd = kb + (wn*16 + b_rp)*144 + (ks*16 + b_ko)*2;
            uint32_t bhi[4], blo[4];
            ldsm4(bhi, bd);
            ldsm4(blo, bd + 18432);
            mma16816(acc[0], qhi[ks], &bhi[0]);
            mma16816(acc[1], qhi[ks], &bhi[2]);
            mma16816(acc[0], qhi[ks], &blo[0]);
            mma16816(acc[1], qhi[ks], &blo[2]);
            mma16816(acc[0], qlo[ks], &bhi[0]);
            mma16816(acc[1], qlo[ks], &bhi[2]);
        }
        #pragma unroll
        for (int nf = 0; nf < 2; ++nf) {
            int key = kt*128 + wn*16 + nf*8 + tc;
            int row0 = wm*16 + tr;
            float2 o;
            o.x = acc[nf][0]*0.125f; o.y = acc[nf][1]*0.125f;
            *(float2*)&smf[SS_OFF + row0*SS_STR + key] = o;
            o.x = acc[nf][2]*0.125f; o.y = acc[nf][3]*0.125f;
            *(float2*)&smf[SS_OFF + (row0+8)*SS_STR + key] = o;
        }
    }
    __syncthreads();
    issue_v(sb, bhoff, 0, 0, tid);       // overlap V(0) load with top-k

    // ---- top-k + softmax (2 rows per warp) ----
    int r0 = 2 * w;
    #pragma unroll 1
    for (int rr = 0; rr < 2; ++rr) {
        float* srow = &smf[SS_OFF + (r0 + rr) * SS_STR];
        unsigned key[32];
        float lmax = -3.4e38f;
        #pragma unroll
        for (int i = 0; i < 32; ++i) {
            float s = srow[lane + 32*i];
            lmax = fmaxf(lmax, s);
            unsigned ub = __float_as_uint(s);
            key[i] = ub ^ (((unsigned)((int)ub >> 31)) | 0x80000000u);
        }
        #pragma unroll
        for (int o = 16; o; o >>= 1) lmax = fmaxf(lmax, __shfl_xor_sync(~0u, lmax, o));
        unsigned lo = 0u, hi = 0xFFFFFFFFu;
        while (lo < hi) {
            unsigned mid = lo + (unsigned)(((unsigned long long)(hi - lo) + 1ull) >> 1);
            unsigned c = 0;
            #pragma unroll
            for (int i = 0; i < 32; ++i) c += (key[i] >= mid) ? 1u : 0u;
            c = __reduce_add_sync(~0u, c);
            if (c >= (unsigned)KSP) lo = mid; else hi = mid - 1u;
        }
        unsigned T = lo;
        float lsum = 0.f;
        #pragma unroll
        for (int i = 0; i < 32; ++i) {
            float e = 0.f;
            if (key[i] >= T) {
                unsigned ub = key[i];
                unsigned fb = ub ^ ((ub & 0x80000000u) ? 0x80000000u : 0xFFFFFFFFu);
                e = __expf(__uint_as_float(fb) - lmax);
            }
            lsum += e;
            srow[lane + 32*i] = e;
        }
        #pragma unroll
        for (int o = 16; o; o >>= 1) lsum += __shfl_xor_sync(~0u, lsum, o);
        float inv = 1.f / lsum;
        #pragma unroll
        for (int i = 0; i < 32; ++i) srow[lane + 32*i] *= inv;
    }

    // ---- phase 2: P @ V (double-buffered V, warp-uniform zero skip) ----
    float o00=0, o01=0, o10=0, o11=0;
    for (int kt = 0; kt < 8; ++kt) {
        CP_WAIT0();
        __syncthreads();
        if (kt < 7) issue_v(sb, bhoff, kt + 1, (kt + 1) & 1, tid);
        const float* sV = smf + 2304 + (kt & 1)*8704;
        const float* pa = &smf[SS_OFF + r0*SS_STR + kt*128];
        const float* pb = pa + SS_STR;
        #pragma unroll 4
        for (int m = 0; m < 128; ++m) {
            float x0 = pa[m];
            if (x0 != 0.f) {
                o00 = fmaf(x0, sV[m*68 + lane     ], o00);
                o01 = fmaf(x0, sV[m*68 + lane + 32], o01);
            }
            float x1 = pb[m];
            if (x1 != 0.f) {
                o10 = fmaf(x1, sV[m*68 + lane     ], o10);
                o11 = fmaf(x1, sV[m*68 + lane + 32], o11);
            }
        }
        __syncthreads();
    }
    int bb = bh >> 4, hh = bh & 15;
    #pragma unroll
    for (int rr = 0; rr < 2; ++rr) {
        size_t base = ((size_t)(bb*1024 + n0 + r0 + rr)) * 1024 + hh*64;
        bf16 h, l;
        bfsplit(rr ? o10 : o00, h, l);
        g_ath[base + lane] = h; g_atl[base + lane] = l;
        bfsplit(rr ? o11 : o01, h, l);
        g_ath[base + lane + 32] = h; g_atl[base + lane + 32] = l;
    }
}

// ---------------- launch ----------------
extern "C" void kernel_launch(void* const* d_in, const int* in_sizes, int n_in,
                              void* d_out, int out_size)
{
    (void)in_sizes; (void)n_in; (void)out_size;
    const float* x     = (const float*)d_in[0];
    const float* ln1_w = (const float*)d_in[1];
    const float* ln1_b = (const float*)d_in[2];
    const float* qkv_w = (const float*)d_in[3];
    const float* qkv_b = (const float*)d_in[4];
    const float* out_w = (const float*)d_in[5];
    const float* out_b = (const float*)d_in[6];
    const float* ln2_w = (const float*)d_in[7];
    const float* ln2_b = (const float*)d_in[8];
    const float* w1    = (const float*)d_in[9];
    const float* b1    = (const float*)d_in[10];
    const float* w2    = (const float*)d_in[11];
    const float* b2    = (const float*)d_in[12];
    const float* mask1 = (const float*)d_in[13];
    const float* mask2 = (const float*)d_in[14];
    float* out = (float*)d_out;

    void *x1, *xnh, *xnl, *hnh, *hnl, *ath, *atl, *h1h, *h1l,
         *qwh, *qwl, *owh, *owl, *w1h, *w1l, *w2h, *w2l;
    cudaGetSymbolAddress(&x1, g_x1);
    cudaGetSymbolAddress(&xnh, g_xnh); cudaGetSymbolAddress(&xnl, g_xnl);
    cudaGetSymbolAddress(&hnh, g_hnh); cudaGetSymbolAddress(&hnl, g_hnl);
    cudaGetSymbolAddress(&ath, g_ath); cudaGetSymbolAddress(&atl, g_atl);
    cudaGetSymbolAddress(&h1h, g_h1h); cudaGetSymbolAddress(&h1l, g_h1l);
    cudaGetSymbolAddress(&qwh, g_qwh); cudaGetSymbolAddress(&qwl, g_qwl);
    cudaGetSymbolAddress(&owh, g_owh); cudaGetSymbolAddress(&owl, g_owl);
    cudaGetSymbolAddress(&w1h, g_w1h); cudaGetSymbolAddress(&w1l, g_w1l);
    cudaGetSymbolAddress(&w2h, g_w2h); cudaGetSymbolAddress(&w2l, g_w2l);

    cudaFuncSetAttribute(attn_kernel, cudaFuncAttributeMaxDynamicSharedMemorySize, ATTN_SMEM);
    cudaFuncSetAttribute(tc_gemm<0>, cudaFuncAttributeMaxDynamicSharedMemorySize, GSMEM);
    cudaFuncSetAttribute(tc_gemm<1>, cudaFuncAttributeMaxDynamicSharedMemorySize, GSMEM);
    cudaFuncSetAttribute(tc_gemm<2>, cudaFuncAttributeMaxDynamicSharedMemorySize, GSMEM);
    cudaFuncSetAttribute(tc_gemm<3>, cudaFuncAttributeMaxDynamicSharedMemorySize, GSMEM);

    cvt_split2<<<4096, 256>>>(qkv_w, (bf16*)qwh, (bf16*)qwl, 786432,
                              out_w, (bf16*)owh, (bf16*)owl, 262144);
    cvt_split2<<<8192, 256>>>(w1, (bf16*)w1h, (bf16*)w1l, 1048576,
                              w2, (bf16*)w2h, (bf16*)w2l, 1048576);

    ln_bf16<<<M_, 256>>>(x, ln1_w, ln1_b, (bf16*)xnh, (bf16*)xnl);

    tc_gemm<0><<<dim3(24, 64), 256, GSMEM>>>((bf16*)xnh, (bf16*)xnl,
        (bf16*)qwh, (bf16*)qwl, qkv_b, nullptr, nullptr, nullptr, nullptr, nullptr,
        3*C_, C_);

    attn_kernel<<<BH_*(N_/32), 512, ATTN_SMEM>>>();

    tc_gemm<1><<<dim3(8, 64), 256, GSMEM>>>((bf16*)ath, (bf16*)atl,
        (bf16*)owh, (bf16*)owl, out_b, nullptr, x, (float*)x1, nullptr, nullptr,
        C_, C_);

    ln_bf16<<<M_, 256>>>((float*)x1, ln2_w, ln2_b, (bf16*)hnh, (bf16*)hnl);

    tc_gemm<2><<<dim3(32, 64), 256, GSMEM>>>((bf16*)hnh, (bf16*)hnl,
        (bf16*)w1h, (bf16*)w1l, b1, mask1, nullptr, nullptr, (bf16*)h1h, (bf16*)h1l,
        FF_, C_);

    tc_gemm<3><<<dim3(8, 64), 256, GSMEM>>>((bf16*)h1h, (bf16*)h1l,
        (bf16*)w2h, (bf16*)w2l, b2, mask2, (float*)x1, out, nullptr, nullptr,
        C_, FF_);
}

// round 8
// speedup vs baseline: 2.1040x; 1.0187x over previous
#include <cuda_runtime.h>
#include <cuda_bf16.h>
#include <stdint.h>

#define B_   8
#define N_   1024
#define C_   1024
#define HD_  64
#define FF_  4096
#define BH_  128
#define M_   8192
#define KSP  102

typedef __nv_bfloat16 bf16;
typedef __nv_bfloat162 bf162;

// ---------------- scratch ----------------
__device__ __align__(256) float g_v[(size_t)BH_*N_*HD_];
__device__ __align__(256) float g_x1[(size_t)M_*C_];
__device__ __align__(256) bf16 g_qh[(size_t)BH_*N_*HD_], g_ql[(size_t)BH_*N_*HD_];
__device__ __align__(256) bf16 g_kh[(size_t)BH_*N_*HD_], g_kl[(size_t)BH_*N_*HD_];
__device__ __align__(256) bf16 g_xnh[(size_t)M_*C_],  g_xnl[(size_t)M_*C_];
__device__ __align__(256) bf16 g_hnh[(size_t)M_*C_],  g_hnl[(size_t)M_*C_];
__device__ __align__(256) bf16 g_ath[(size_t)M_*C_],  g_atl[(size_t)M_*C_];
__device__ __align__(256) bf16 g_h1h[(size_t)M_*FF_], g_h1l[(size_t)M_*FF_];
__device__ __align__(256) bf16 g_qwh[(size_t)3*C_*C_], g_qwl[(size_t)3*C_*C_];
__device__ __align__(256) bf16 g_owh[(size_t)C_*C_],   g_owl[(size_t)C_*C_];
__device__ __align__(256) bf16 g_w1h[(size_t)FF_*C_],  g_w1l[(size_t)FF_*C_];
__device__ __align__(256) bf16 g_w2h[(size_t)C_*FF_],  g_w2l[(size_t)C_*FF_];

// ---------------- helpers ----------------
__device__ __forceinline__ uint32_t s2u(const void* p) {
    uint32_t a;
    asm("{ .reg .u64 t; cvta.to.shared.u64 t, %1; cvt.u32.u64 %0, t; }" : "=r"(a) : "l"(p));
    return a;
}
__device__ __forceinline__ void bfsplit(float v, bf16& h, bf16& l) {
    h = __float2bfloat16(v);
    l = __float2bfloat16(v - __bfloat162float(h));
}
__device__ __forceinline__ void ldsm4(uint32_t* r, uint32_t a) {
    asm volatile("ldmatrix.sync.aligned.m8n8.x4.shared.b16 {%0,%1,%2,%3}, [%4];"
        : "=r"(r[0]), "=r"(r[1]), "=r"(r[2]), "=r"(r[3]) : "r"(a));
}
__device__ __forceinline__ void mma16816(float* c, const uint32_t* a, const uint32_t* b) {
    asm volatile("mma.sync.aligned.m16n8k16.row.col.f32.bf16.bf16.f32 "
        "{%0,%1,%2,%3}, {%4,%5,%6,%7}, {%8,%9}, {%0,%1,%2,%3};"
        : "+f"(c[0]), "+f"(c[1]), "+f"(c[2]), "+f"(c[3])
        : "r"(a[0]), "r"(a[1]), "r"(a[2]), "r"(a[3]), "r"(b[0]), "r"(b[1]));
}
#define CP_ASYNC16(s, g) \
    asm volatile("cp.async.cg.shared.global [%0], [%1], 16;" :: "r"(s), "l"(g))
#define CP_COMMIT() asm volatile("cp.async.commit_group;" ::: "memory")
#define CP_WAIT0()  asm volatile("cp.async.wait_group 0;" ::: "memory")

// ---------------- weight split: ALL four weights in ONE launch ------------
__global__ void __launch_bounds__(256)
cvt4(const float* __restrict__ s0, bf16* __restrict__ h0, bf16* __restrict__ l0, int n0,
     const float* __restrict__ s1, bf16* __restrict__ h1, bf16* __restrict__ l1, int n1,
     const float* __restrict__ s2, bf16* __restrict__ h2, bf16* __restrict__ l2, int n2,
     const float* __restrict__ s3, bf16* __restrict__ h3, bf16* __restrict__ l3, int n3)
{
    int i = blockIdx.x * 256 + threadIdx.x;
    const float* s; bf16 *h, *l;
    if (i < n0) { s = s0; h = h0; l = l0; }
    else if ((i -= n0) < n1) { s = s1; h = h1; l = l1; }
    else if ((i -= n1) < n2) { s = s2; h = h2; l = l2; }
    else { i -= n2; if (i >= n3) return; s = s3; h = h3; l = l3; }
    float4 v = ((const float4*)s)[i];
    bf16 a0,a1,a2,a3,b0,b1,b2,b3;
    bfsplit(v.x,a0,b0); bfsplit(v.y,a1,b1); bfsplit(v.z,a2,b2); bfsplit(v.w,a3,b3);
    bf162 p,q;
    p.x=a0;p.y=a1;q.x=a2;q.y=a3; ((bf162*)h)[i*2]=p; ((bf162*)h)[i*2+1]=q;
    p.x=b0;p.y=b1;q.x=b2;q.y=b3; ((bf162*)l)[i*2]=p; ((bf162*)l)[i*2+1]=q;
}

// ---------------- LayerNorm -> bf16 hi/lo ----------------
__global__ void __launch_bounds__(256)
ln_bf16(const float* __restrict__ x, const float* __restrict__ w,
        const float* __restrict__ b, bf16* __restrict__ yh, bf16* __restrict__ yl)
{
    __shared__ float red[16];
    int row = blockIdx.x, t = threadIdx.x;
    float4 v = ((const float4*)(x + (size_t)row * 1024))[t];
    float s  = v.x + v.y + v.z + v.w;
    float ss = v.x*v.x + v.y*v.y + v.z*v.z + v.w*v.w;
    #pragma unroll
    for (int o = 16; o; o >>= 1) {
        s  += __shfl_xor_sync(~0u, s, o);
        ss += __shfl_xor_sync(~0u, ss, o);
    }
    if ((t & 31) == 0) { red[t>>5] = s; red[(t>>5)+8] = ss; }
    __syncthreads();
    if (t == 0) {
        float ts=0.f, tss=0.f;
        #pragma unroll
        for (int i = 0; i < 8; ++i) { ts += red[i]; tss += red[i+8]; }
        float mu = ts * (1.f/1024.f);
        red[0] = mu; red[1] = rsqrtf(tss*(1.f/1024.f) - mu*mu + 1e-5f);
    }
    __syncthreads();
    float mu = red[0], rs = red[1];
    float4 wv = ((const float4*)w)[t];
    float4 bv = ((const float4*)b)[t];
    float o0 = (v.x-mu)*rs*wv.x + bv.x, o1 = (v.y-mu)*rs*wv.y + bv.y;
    float o2 = (v.z-mu)*rs*wv.z + bv.z, o3 = (v.w-mu)*rs*wv.w + bv.w;
    bf16 h0,h1,h2,h3,l0,l1,l2,l3;
    bfsplit(o0,h0,l0); bfsplit(o1,h1,l1); bfsplit(o2,h2,l2); bfsplit(o3,h3,l3);
    size_t oi = ((size_t)row*1024 + t*4) >> 1;
    bf162 pa, pb;
    pa.x=h0;pa.y=h1;pb.x=h2;pb.y=h3; ((bf162*)yh)[oi]=pa; ((bf162*)yh)[oi+1]=pb;
    pa.x=l0;pa.y=l1;pb.x=l2;pb.y=l3; ((bf162*)yl)[oi]=pa; ((bf162*)yl)[oi+1]=pb;
}

// ---- HMMA GEMM: 128x128 tile, 256 thr, 2-stage, 2 CTAs/SM, bf16x3 ----
// inner loop restructured: 3 passes of 16 independent MMAs (dep distance 16)
#define ATILE_B  10240
#define STAGE_B  40960
#define GSMEM    (2*STAGE_B)

__device__ __forceinline__ void issue_stage(
    const bf16* __restrict__ Ah, const bf16* __restrict__ Al,
    const bf16* __restrict__ Bh, const bf16* __restrict__ Bl,
    uint32_t sbase, int bm, int bn, int ko, int K, int tid)
{
    #pragma unroll
    for (int i = 0; i < 8; ++i) {
        int lin = tid + (i << 8);
        int tile = lin >> 9;
        int wit = lin & 511;
        int r = wit >> 2, ch = wit & 3;
        const bf16* gp;
        if      (tile == 0) gp = Ah + (size_t)(bm + r) * K + ko + ch*8;
        else if (tile == 1) gp = Al + (size_t)(bm + r) * K + ko + ch*8;
        else if (tile == 2) gp = Bh + (size_t)(bn + r) * K + ko + ch*8;
        else                gp = Bl + (size_t)(bn + r) * K + ko + ch*8;
        CP_ASYNC16(sbase + tile*ATILE_B + r*80 + ch*16, gp);
    }
    CP_COMMIT();
}

template<int EPI>
__global__ void __launch_bounds__(256, 2)
tc_gemm(const bf16* __restrict__ Ah, const bf16* __restrict__ Al,
        const bf16* __restrict__ Bh, const bf16* __restrict__ Bl,
        const float* __restrict__ bias, const float* __restrict__ aux,
        const float* __restrict__ res, float* __restrict__ outf,
        bf16* __restrict__ outh, bf16* __restrict__ outl, int N, int K)
{
    extern __shared__ char smem[];
    uint32_t sb = s2u(smem);
    const int tid = threadIdx.x, lane = tid & 31, wid = tid >> 5;
    const int wm = wid & 3, wn = wid >> 2;
    const int bm = blockIdx.y << 7, bn = blockIdx.x << 7;

    float acc[2][8][4];
    #pragma unroll
    for (int i = 0; i < 2; ++i)
        #pragma unroll
        for (int j = 0; j < 8; ++j)
            #pragma unroll
            for (int q = 0; q < 4; ++q) acc[i][j][q] = 0.f;

    const int ktn = K >> 5;
    issue_stage(Ah, Al, Bh, Bl, sb, bm, bn, 0, K, tid);

    const int a_ro = (lane & 15);
    const int a_ko = (lane >> 4) * 8;
    const int b_rp = ((lane >> 4) & 1) * 8 + (lane & 7);
    const int b_ko = ((lane >> 3) & 1) * 8;

    for (int kt = 0; kt < ktn; ++kt) {
        CP_WAIT0();
        __syncthreads();
        if (kt + 1 < ktn)
            issue_stage(Ah, Al, Bh, Bl, sb + ((kt + 1) & 1) * STAGE_B,
                        bm, bn, (kt + 1) * 32, K, tid);
        uint32_t st = sb + (kt & 1) * STAGE_B;
        #pragma unroll
        for (int ks = 0; ks < 2; ++ks) {
            uint32_t ahi[2][4], alo[2][4], bhi[4][4], blo[4][4];
            // stage A-hi + B-hi fragments
            #pragma unroll
            for (int mf = 0; mf < 2; ++mf)
                ldsm4(ahi[mf], st + (wm*32 + mf*16 + a_ro)*80 + (ks*16 + a_ko)*2);
            #pragma unroll
            for (int np = 0; np < 4; ++np)
                ldsm4(bhi[np], st + 2*ATILE_B + (wn*64 + np*16 + b_rp)*80 + (ks*16 + b_ko)*2);
            // pass 1: hi*hi — 16 independent MMAs
            #pragma unroll
            for (int np = 0; np < 4; ++np)
                #pragma unroll
                for (int mf = 0; mf < 2; ++mf) {
                    mma16816(acc[mf][np*2  ], ahi[mf], &bhi[np][0]);
                    mma16816(acc[mf][np*2+1], ahi[mf], &bhi[np][2]);
                }
            // stage B-lo
            #pragma unroll
            for (int np = 0; np < 4; ++np)
                ldsm4(blo[np], st + 2*ATILE_B + ATILE_B + (wn*64 + np*16 + b_rp)*80 + (ks*16 + b_ko)*2);
            // pass 2: hi*lo
            #pragma unroll
            for (int np = 0; np < 4; ++np)
                #pragma unroll
                for (int mf = 0; mf < 2; ++mf) {
                    mma16816(acc[mf][np*2  ], ahi[mf], &blo[np][0]);
                    mma16816(acc[mf][np*2+1], ahi[mf], &blo[np][2]);
                }
            // stage A-lo
            #pragma unroll
            for (int mf = 0; mf < 2; ++mf)
                ldsm4(alo[mf], st + ATILE_B + (wm*32 + mf*16 + a_ro)*80 + (ks*16 + a_ko)*2);
            // pass 3: lo*hi
            #pragma unroll
            for (int np = 0; np < 4; ++np)
                #pragma unroll
                for (int mf = 0; mf < 2; ++mf) {
                    mma16816(acc[mf][np*2  ], alo[mf], &bhi[np][0]);
                    mma16816(acc[mf][np*2+1], alo[mf], &bhi[np][2]);
                }
        }
    }

    const int tr = lane >> 2;
    const int tc = (lane & 3) * 2;
    #pragma unroll
    for (int mf = 0; mf < 2; ++mf) {
        #pragma unroll
        for (int nf = 0; nf < 8; ++nf) {
            int gj = bn + wn*64 + nf*8 + tc;
            float2 b2 = *(const float2*)&bias[gj];
            #pragma unroll
            for (int h = 0; h < 2; ++h) {
                int gi = bm + wm*32 + mf*16 + tr + h*8;
                float v0 = acc[mf][nf][h*2]   + b2.x;
                float v1 = acc[mf][nf][h*2+1] + b2.y;
                size_t off = (size_t)gi * N + gj;
                if (EPI == 0) {
                    int wh = gj >> 10, hh = (gj >> 6) & 15, d = gj & 63;
                    int bb = gi >> 10, nn = gi & 1023;
                    size_t idx = (((size_t)(bb*16 + hh))*1024 + nn)*64 + d;
                    if (wh == 2) {
                        float2 o; o.x = v0; o.y = v1;
                        *(float2*)&g_v[idx] = o;
                    } else {
                        bf16 h0,l0,h1,l1;
                        bfsplit(v0,h0,l0); bfsplit(v1,h1,l1);
                        bf162 ph, pl; ph.x=h0; ph.y=h1; pl.x=l0; pl.y=l1;
                        if (wh == 0) { *(bf162*)&g_qh[idx]=ph; *(bf162*)&g_ql[idx]=pl; }
                        else         { *(bf162*)&g_kh[idx]=ph; *(bf162*)&g_kl[idx]=pl; }
                    }
                } else if (EPI == 1) {
                    float2 rr = *(const float2*)&res[off];
                    float2 o; o.x = v0 + rr.x; o.y = v1 + rr.y;
                    *(float2*)&outf[off] = o;
                } else if (EPI == 2) {
                    float2 m = *(const float2*)&aux[off];
                    v0 = (m.x > 0.5f) ? fmaxf(v0, 0.f) : 0.f;
                    v1 = (m.y > 0.5f) ? fmaxf(v1, 0.f) : 0.f;
                    bf16 h0,l0,h1,l1;
                    bfsplit(v0,h0,l0); bfsplit(v1,h1,l1);
                    bf162 p; p.x=h0; p.y=h1; *(bf162*)&outh[off] = p;
                    p.x=l0; p.y=l1;          *(bf162*)&outl[off] = p;
                } else {
                    float2 m  = *(const float2*)&aux[off];
                    float2 rr = *(const float2*)&res[off];
                    float2 o;
                    o.x = rr.x + ((m.x > 0.5f) ? v0 : 0.f);
                    o.y = rr.y + ((m.y > 0.5f) ? v1 : 0.f);
                    *(float2*)&outf[off] = o;
                }
            }
        }
    }
}

// ------- sparse attention: cp.async double-buffered K/V, HMMA scores -------
#define SS_STR  1034
#define SS_OFF  20736
#define ATTN_SMEM (9216 + 73728 + 32*SS_STR*4)

__device__ __forceinline__ void issue_k(uint32_t sb, size_t bhoff, int kt, int buf, int tid) {
    #pragma unroll
    for (int i = 0; i < 4; ++i) {
        int lin = tid + (i << 9);
        int tile = lin >> 10, wit = lin & 1023;
        int r = wit >> 3, ch = wit & 7;
        const bf16* gsrc = (tile ? g_kl : g_kh) + bhoff + (size_t)(kt*128 + r)*64 + ch*8;
        CP_ASYNC16(sb + 9216 + buf*36864 + tile*18432 + r*144 + ch*16, gsrc);
    }
    CP_COMMIT();
}
__device__ __forceinline__ void issue_v(uint32_t sb, size_t bhoff, int kt, int buf, int tid) {
    #pragma unroll
    for (int i = 0; i < 4; ++i) {
        int lin = tid + (i << 9);
        int r = lin >> 4, ch = lin & 15;
        const float* gsrc = &g_v[bhoff + (size_t)(kt*128 + r)*64 + ch*4];
        CP_ASYNC16(sb + 9216 + buf*34816 + r*272 + ch*16, gsrc);
    }
    CP_COMMIT();
}

__global__ void __launch_bounds__(512)
attn_kernel()
{
    extern __shared__ char smraw[];
    float* smf = (float*)smraw;
    uint32_t sb = s2u(smraw);

    int blk = blockIdx.x, bh = blk >> 5, n0 = (blk & 31) << 5;
    int tid = threadIdx.x, lane = tid & 31, w = tid >> 5;
    const size_t bhoff = (size_t)bh * 65536;

    {
        int tile = tid >> 8, wit = tid & 255, r = wit >> 3, ch = wit & 7;
        const bf16* gsrc = (tile ? g_ql : g_qh) + bhoff + (size_t)(n0 + r)*64 + ch*8;
        *(uint4*)(smraw + tile*4608 + r*144 + ch*16) = *(const uint4*)gsrc;
    }
    issue_k(sb, bhoff, 0, 0, tid);
    __syncthreads();

    const int wm = w & 1, wn = w >> 1;
    const int a_ro = lane & 15, a_ko = (lane >> 4) * 8;
    const int b_rp = ((lane >> 4) & 1) * 8 + (lane & 7);
    const int b_ko = ((lane >> 3) & 1) * 8;
    uint32_t qhi[4][4], qlo[4][4];
    #pragma unroll
    for (int ks = 0; ks < 4; ++ks) {
        uint32_t qa = sb + (wm*16 + a_ro)*144 + (ks*16 + a_ko)*2;
        ldsm4(qhi[ks], qa);
        ldsm4(qlo[ks], qa + 4608);
    }
    const int tr = lane >> 2, tc = (lane & 3) * 2;

    for (int kt = 0; kt < 8; ++kt) {
        CP_WAIT0();
        __syncthreads();
        if (kt < 7) issue_k(sb, bhoff, kt + 1, (kt + 1) & 1, tid);
        uint32_t kb = sb + 9216 + (kt & 1)*36864;
        float acc[2][4];
        #pragma unroll
        for (int nf = 0; nf < 2; ++nf)
            #pragma unroll
            for (int q = 0; q < 4; ++q) acc[nf][q] = 0.f;
        #pragma unroll
        for (int ks = 0; ks < 4; ++ks) {
            uint32_t bd = kb + (wn*16 + b_rp)*144 + (ks*16 + b_ko)*2;
            uint32_t bhi[4], blo[4];
            ldsm4(bhi, bd);
            ldsm4(blo, bd + 18432);
            mma16816(acc[0], qhi[ks], &bhi[0]);
            mma16816(acc[1], qhi[ks], &bhi[2]);
            mma16816(acc[0], qhi[ks], &blo[0]);
            mma16816(acc[1], qhi[ks], &blo[2]);
            mma16816(acc[0], qlo[ks], &bhi[0]);
            mma16816(acc[1], qlo[ks], &bhi[2]);
        }
        #pragma unroll
        for (int nf = 0; nf < 2; ++nf) {
            int key = kt*128 + wn*16 + nf*8 + tc;
            int row0 = wm*16 + tr;
            float2 o;
            o.x = acc[nf][0]*0.125f; o.y = acc[nf][1]*0.125f;
            *(float2*)&smf[SS_OFF + row0*SS_STR + key] = o;
            o.x = acc[nf][2]*0.125f; o.y = acc[nf][3]*0.125f;
            *(float2*)&smf[SS_OFF + (row0+8)*SS_STR + key] = o;
        }
    }
    __syncthreads();
    issue_v(sb, bhoff, 0, 0, tid);

    int r0 = 2 * w;
    #pragma unroll 1
    for (int rr = 0; rr < 2; ++rr) {
        float* srow = &smf[SS_OFF + (r0 + rr) * SS_STR];
        unsigned key[32];
        float lmax = -3.4e38f;
        #pragma unroll
        for (int i = 0; i < 32; ++i) {
            float s = srow[lane + 32*i];
            lmax = fmaxf(lmax, s);
            unsigned ub = __float_as_uint(s);
            key[i] = ub ^ (((unsigned)((int)ub >> 31)) | 0x80000000u);
        }
        #pragma unroll
        for (int o = 16; o; o >>= 1) lmax = fmaxf(lmax, __shfl_xor_sync(~0u, lmax, o));
        unsigned lo = 0u, hi = 0xFFFFFFFFu;
        while (lo < hi) {
            unsigned mid = lo + (unsigned)(((unsigned long long)(hi - lo) + 1ull) >> 1);
            unsigned c = 0;
            #pragma unroll
            for (int i = 0; i < 32; ++i) c += (key[i] >= mid) ? 1u : 0u;
            c = __reduce_add_sync(~0u, c);
            if (c >= (unsigned)KSP) lo = mid; else hi = mid - 1u;
        }
        unsigned T = lo;
        float lsum = 0.f;
        #pragma unroll
        for (int i = 0; i < 32; ++i) {
            float e = 0.f;
            if (key[i] >= T) {
                unsigned ub = key[i];
                unsigned fb = ub ^ ((ub & 0x80000000u) ? 0x80000000u : 0xFFFFFFFFu);
                e = __expf(__uint_as_float(fb) - lmax);
            }
            lsum += e;
            srow[lane + 32*i] = e;
        }
        #pragma unroll
        for (int o = 16; o; o >>= 1) lsum += __shfl_xor_sync(~0u, lsum, o);
        float inv = 1.f / lsum;
        #pragma unroll
        for (int i = 0; i < 32; ++i) srow[lane + 32*i] *= inv;
    }

    float o00=0, o01=0, o10=0, o11=0;
    for (int kt = 0; kt < 8; ++kt) {
        CP_WAIT0();
        __syncthreads();
        if (kt < 7) issue_v(sb, bhoff, kt + 1, (kt + 1) & 1, tid);
        const float* sV = smf + 2304 + (kt & 1)*8704;
        const float* pa = &smf[SS_OFF + r0*SS_STR + kt*128];
        const float* pb = pa + SS_STR;
        #pragma unroll 4
        for (int m = 0; m < 128; ++m) {
            float x0 = pa[m];
            if (x0 != 0.f) {
                o00 = fmaf(x0, sV[m*68 + lane     ], o00);
                o01 = fmaf(x0, sV[m*68 + lane + 32], o01);
            }
            float x1 = pb[m];
            if (x1 != 0.f) {
                o10 = fmaf(x1, sV[m*68 + lane     ], o10);
                o11 = fmaf(x1, sV[m*68 + lane + 32], o11);
            }
        }
        __syncthreads();
    }
    int bb = bh >> 4, hh = bh & 15;
    #pragma unroll
    for (int rr = 0; rr < 2; ++rr) {
        size_t base = ((size_t)(bb*1024 + n0 + r0 + rr)) * 1024 + hh*64;
        bf16 h, l;
        bfsplit(rr ? o10 : o00, h, l);
        g_ath[base + lane] = h; g_atl[base + lane] = l;
        bfsplit(rr ? o11 : o01, h, l);
        g_ath[base + lane + 32] = h; g_atl[base + lane + 32] = l;
    }
}

// ---------------- launch ----------------
extern "C" void kernel_launch(void* const* d_in, const int* in_sizes, int n_in,
                              void* d_out, int out_size)
{
    (void)in_sizes; (void)n_in; (void)out_size;
    const float* x     = (const float*)d_in[0];
    const float* ln1_w = (const float*)d_in[1];
    const float* ln1_b = (const float*)d_in[2];
    const float* qkv_w = (const float*)d_in[3];
    const float* qkv_b = (const float*)d_in[4];
    const float* out_w = (const float*)d_in[5];
    const float* out_b = (const float*)d_in[6];
    const float* ln2_w = (const float*)d_in[7];
    const float* ln2_b = (const float*)d_in[8];
    const float* w1    = (const float*)d_in[9];
    const float* b1    = (const float*)d_in[10];
    const float* w2    = (const float*)d_in[11];
    const float* b2    = (const float*)d_in[12];
    const float* mask1 = (const float*)d_in[13];
    const float* mask2 = (const float*)d_in[14];
    float* out = (float*)d_out;

    void *x1, *xnh, *xnl, *hnh, *hnl, *ath, *atl, *h1h, *h1l,
         *qwh, *qwl, *owh, *owl, *w1h, *w1l, *w2h, *w2l;
    cudaGetSymbolAddress(&x1, g_x1);
    cudaGetSymbolAddress(&xnh, g_xnh); cudaGetSymbolAddress(&xnl, g_xnl);
    cudaGetSymbolAddress(&hnh, g_hnh); cudaGetSymbolAddress(&hnl, g_hnl);
    cudaGetSymbolAddress(&ath, g_ath); cudaGetSymbolAddress(&atl, g_atl);
    cudaGetSymbolAddress(&h1h, g_h1h); cudaGetSymbolAddress(&h1l, g_h1l);
    cudaGetSymbolAddress(&qwh, g_qwh); cudaGetSymbolAddress(&qwl, g_qwl);
    cudaGetSymbolAddress(&owh, g_owh); cudaGetSymbolAddress(&owl, g_owl);
    cudaGetSymbolAddress(&w1h, g_w1h); cudaGetSymbolAddress(&w1l, g_w1l);
    cudaGetSymbolAddress(&w2h, g_w2h); cudaGetSymbolAddress(&w2l, g_w2l);

    cudaFuncSetAttribute(attn_kernel, cudaFuncAttributeMaxDynamicSharedMemorySize, ATTN_SMEM);
    cudaFuncSetAttribute(tc_gemm<0>, cudaFuncAttributeMaxDynamicSharedMemorySize, GSMEM);
    cudaFuncSetAttribute(tc_gemm<1>, cudaFuncAttributeMaxDynamicSharedMemorySize, GSMEM);
    cudaFuncSetAttribute(tc_gemm<2>, cudaFuncAttributeMaxDynamicSharedMemorySize, GSMEM);
    cudaFuncSetAttribute(tc_gemm<3>, cudaFuncAttributeMaxDynamicSharedMemorySize, GSMEM);

    // launch order: [0]cvt4 [1]ln1 [2]gemm0 [3]attn  -> ncu captures attn
    cvt4<<<12288, 256>>>(qkv_w, (bf16*)qwh, (bf16*)qwl, 786432,
                         out_w, (bf16*)owh, (bf16*)owl, 262144,
                         w1,    (bf16*)w1h, (bf16*)w1l, 1048576,
                         w2,    (bf16*)w2h, (bf16*)w2l, 1048576);

    ln_bf16<<<M_, 256>>>(x, ln1_w, ln1_b, (bf16*)xnh, (bf16*)xnl);

    tc_gemm<0><<<dim3(24, 64), 256, GSMEM>>>((bf16*)xnh, (bf16*)xnl,
        (bf16*)qwh, (bf16*)qwl, qkv_b, nullptr, nullptr, nullptr, nullptr, nullptr,
        3*C_, C_);

    attn_kernel<<<BH_*(N_/32), 512, ATTN_SMEM>>>();

    tc_gemm<1><<<dim3(8, 64), 256, GSMEM>>>((bf16*)ath, (bf16*)atl,
        (bf16*)owh, (bf16*)owl, out_b, nullptr, x, (float*)x1, nullptr, nullptr,
        C_, C_);

    ln_bf16<<<M_, 256>>>((float*)x1, ln2_w, ln2_b, (bf16*)hnh, (bf16*)hnl);

    tc_gemm<2><<<dim3(32, 64), 256, GSMEM>>>((bf16*)hnh, (bf16*)hnl,
        (bf16*)w1h, (bf16*)w1l, b1, mask1, nullptr, nullptr, (bf16*)h1h, (bf16*)h1l,
        FF_, C_);

    tc_gemm<3><<<dim3(8, 64), 256, GSMEM>>>((bf16*)h1h, (bf16*)h1l,
        (bf16*)w2h, (bf16*)w2l, b2, mask2, (float*)x1, out, nullptr, nullptr,
        C_, FF_);
}

// round 9
// speedup vs baseline: 2.9199x; 1.3878x over previous
#include <cuda_runtime.h>
#include <cuda_bf16.h>
#include <stdint.h>

#define B_   8
#define N_   1024
#define C_   1024
#define HD_  64
#define FF_  4096
#define BH_  128
#define M_   8192
#define KSP  102

typedef __nv_bfloat16 bf16;
typedef __nv_bfloat162 bf162;

// ---------------- scratch ----------------
__device__ __align__(256) float g_v[(size_t)BH_*N_*HD_];
__device__ __align__(256) float g_x1[(size_t)M_*C_];
__device__ __align__(256) bf16 g_qh[(size_t)BH_*N_*HD_], g_ql[(size_t)BH_*N_*HD_];
__device__ __align__(256) bf16 g_kh[(size_t)BH_*N_*HD_], g_kl[(size_t)BH_*N_*HD_];
__device__ __align__(256) bf16 g_xnh[(size_t)M_*C_],  g_xnl[(size_t)M_*C_];
__device__ __align__(256) bf16 g_hnh[(size_t)M_*C_],  g_hnl[(size_t)M_*C_];
__device__ __align__(256) bf16 g_ath[(size_t)M_*C_],  g_atl[(size_t)M_*C_];
__device__ __align__(256) bf16 g_h1h[(size_t)M_*FF_], g_h1l[(size_t)M_*FF_];
__device__ __align__(256) bf16 g_qwh[(size_t)3*C_*C_], g_qwl[(size_t)3*C_*C_];
__device__ __align__(256) bf16 g_owh[(size_t)C_*C_],   g_owl[(size_t)C_*C_];
__device__ __align__(256) bf16 g_w1h[(size_t)FF_*C_],  g_w1l[(size_t)FF_*C_];
__device__ __align__(256) bf16 g_w2h[(size_t)C_*FF_],  g_w2l[(size_t)C_*FF_];

// ---------------- helpers ----------------
__device__ __forceinline__ uint32_t s2u(const void* p) {
    uint32_t a;
    asm("{ .reg .u64 t; cvta.to.shared.u64 t, %1; cvt.u32.u64 %0, t; }" : "=r"(a) : "l"(p));
    return a;
}
__device__ __forceinline__ void bfsplit(float v, bf16& h, bf16& l) {
    h = __float2bfloat16(v);
    l = __float2bfloat16(v - __bfloat162float(h));
}
__device__ __forceinline__ void ldsm4(uint32_t* r, uint32_t a) {
    asm volatile("ldmatrix.sync.aligned.m8n8.x4.shared.b16 {%0,%1,%2,%3}, [%4];"
        : "=r"(r[0]), "=r"(r[1]), "=r"(r[2]), "=r"(r[3]) : "r"(a));
}
__device__ __forceinline__ void mma16816(float* c, const uint32_t* a, const uint32_t* b) {
    asm volatile("mma.sync.aligned.m16n8k16.row.col.f32.bf16.bf16.f32 "
        "{%0,%1,%2,%3}, {%4,%5,%6,%7}, {%8,%9}, {%0,%1,%2,%3};"
        : "+f"(c[0]), "+f"(c[1]), "+f"(c[2]), "+f"(c[3])
        : "r"(a[0]), "r"(a[1]), "r"(a[2]), "r"(a[3]), "r"(b[0]), "r"(b[1]));
}
#define CP_ASYNC16(s, g) \
    asm volatile("cp.async.cg.shared.global [%0], [%1], 16;" :: "r"(s), "l"(g))
#define CP_COMMIT() asm volatile("cp.async.commit_group;" ::: "memory")
#define CP_WAIT0()  asm volatile("cp.async.wait_group 0;" ::: "memory")

// ---------------- weight split: ALL four weights in ONE launch ------------
__global__ void __launch_bounds__(256)
cvt4(const float* __restrict__ s0, bf16* __restrict__ h0, bf16* __restrict__ l0, int n0,
     const float* __restrict__ s1, bf16* __restrict__ h1, bf16* __restrict__ l1, int n1,
     const float* __restrict__ s2, bf16* __restrict__ h2, bf16* __restrict__ l2, int n2,
     const float* __restrict__ s3, bf16* __restrict__ h3, bf16* __restrict__ l3, int n3)
{
    int i = blockIdx.x * 256 + threadIdx.x;
    const float* s; bf16 *h, *l;
    if (i < n0) { s = s0; h = h0; l = l0; }
    else if ((i -= n0) < n1) { s = s1; h = h1; l = l1; }
    else if ((i -= n1) < n2) { s = s2; h = h2; l = l2; }
    else { i -= n2; if (i >= n3) return; s = s3; h = h3; l = l3; }
    float4 v = ((const float4*)s)[i];
    bf16 a0,a1,a2,a3,b0,b1,b2,b3;
    bfsplit(v.x,a0,b0); bfsplit(v.y,a1,b1); bfsplit(v.z,a2,b2); bfsplit(v.w,a3,b3);
    bf162 p,q;
    p.x=a0;p.y=a1;q.x=a2;q.y=a3; ((bf162*)h)[i*2]=p; ((bf162*)h)[i*2+1]=q;
    p.x=b0;p.y=b1;q.x=b2;q.y=b3; ((bf162*)l)[i*2]=p; ((bf162*)l)[i*2+1]=q;
}

// ---------------- LayerNorm -> bf16 hi/lo ----------------
__global__ void __launch_bounds__(256)
ln_bf16(const float* __restrict__ x, const float* __restrict__ w,
        const float* __restrict__ b, bf16* __restrict__ yh, bf16* __restrict__ yl)
{
    __shared__ float red[16];
    int row = blockIdx.x, t = threadIdx.x;
    float4 v = ((const float4*)(x + (size_t)row * 1024))[t];
    float s  = v.x + v.y + v.z + v.w;
    float ss = v.x*v.x + v.y*v.y + v.z*v.z + v.w*v.w;
    #pragma unroll
    for (int o = 16; o; o >>= 1) {
        s  += __shfl_xor_sync(~0u, s, o);
        ss += __shfl_xor_sync(~0u, ss, o);
    }
    if ((t & 31) == 0) { red[t>>5] = s; red[(t>>5)+8] = ss; }
    __syncthreads();
    if (t == 0) {
        float ts=0.f, tss=0.f;
        #pragma unroll
        for (int i = 0; i < 8; ++i) { ts += red[i]; tss += red[i+8]; }
        float mu = ts * (1.f/1024.f);
        red[0] = mu; red[1] = rsqrtf(tss*(1.f/1024.f) - mu*mu + 1e-5f);
    }
    __syncthreads();
    float mu = red[0], rs = red[1];
    float4 wv = ((const float4*)w)[t];
    float4 bv = ((const float4*)b)[t];
    float o0 = (v.x-mu)*rs*wv.x + bv.x, o1 = (v.y-mu)*rs*wv.y + bv.y;
    float o2 = (v.z-mu)*rs*wv.z + bv.z, o3 = (v.w-mu)*rs*wv.w + bv.w;
    bf16 h0,h1,h2,h3,l0,l1,l2,l3;
    bfsplit(o0,h0,l0); bfsplit(o1,h1,l1); bfsplit(o2,h2,l2); bfsplit(o3,h3,l3);
    size_t oi = ((size_t)row*1024 + t*4) >> 1;
    bf162 pa, pb;
    pa.x=h0;pa.y=h1;pb.x=h2;pb.y=h3; ((bf162*)yh)[oi]=pa; ((bf162*)yh)[oi+1]=pb;
    pa.x=l0;pa.y=l1;pb.x=l2;pb.y=l3; ((bf162*)yl)[oi]=pa; ((bf162*)yl)[oi+1]=pb;
}

// ---- HMMA GEMM: 128x128 tile, 256 thr, 2-stage, 2 CTAs/SM, bf16x3 ----
#define ATILE_B  10240
#define STAGE_B  40960
#define GSMEM    (2*STAGE_B)

__device__ __forceinline__ void issue_stage(
    const bf16* __restrict__ Ah, const bf16* __restrict__ Al,
    const bf16* __restrict__ Bh, const bf16* __restrict__ Bl,
    uint32_t sbase, int bm, int bn, int ko, int K, int tid)
{
    #pragma unroll
    for (int i = 0; i < 8; ++i) {
        int lin = tid + (i << 8);
        int tile = lin >> 9;
        int wit = lin & 511;
        int r = wit >> 2, ch = wit & 3;
        const bf16* gp;
        if      (tile == 0) gp = Ah + (size_t)(bm + r) * K + ko + ch*8;
        else if (tile == 1) gp = Al + (size_t)(bm + r) * K + ko + ch*8;
        else if (tile == 2) gp = Bh + (size_t)(bn + r) * K + ko + ch*8;
        else                gp = Bl + (size_t)(bn + r) * K + ko + ch*8;
        CP_ASYNC16(sbase + tile*ATILE_B + r*80 + ch*16, gp);
    }
    CP_COMMIT();
}

template<int EPI>
__global__ void __launch_bounds__(256, 2)
tc_gemm(const bf16* __restrict__ Ah, const bf16* __restrict__ Al,
        const bf16* __restrict__ Bh, const bf16* __restrict__ Bl,
        const float* __restrict__ bias, const float* __restrict__ aux,
        const float* __restrict__ res, float* __restrict__ outf,
        bf16* __restrict__ outh, bf16* __restrict__ outl, int N, int K)
{
    extern __shared__ char smem[];
    uint32_t sb = s2u(smem);
    const int tid = threadIdx.x, lane = tid & 31, wid = tid >> 5;
    const int wm = wid & 3, wn = wid >> 2;
    const int bm = blockIdx.y << 7, bn = blockIdx.x << 7;

    float acc[2][8][4];
    #pragma unroll
    for (int i = 0; i < 2; ++i)
        #pragma unroll
        for (int j = 0; j < 8; ++j)
            #pragma unroll
            for (int q = 0; q < 4; ++q) acc[i][j][q] = 0.f;

    const int ktn = K >> 5;
    issue_stage(Ah, Al, Bh, Bl, sb, bm, bn, 0, K, tid);

    const int a_ro = (lane & 15);
    const int a_ko = (lane >> 4) * 8;
    const int b_rp = ((lane >> 4) & 1) * 8 + (lane & 7);
    const int b_ko = ((lane >> 3) & 1) * 8;

    for (int kt = 0; kt < ktn; ++kt) {
        CP_WAIT0();
        __syncthreads();
        if (kt + 1 < ktn)
            issue_stage(Ah, Al, Bh, Bl, sb + ((kt + 1) & 1) * STAGE_B,
                        bm, bn, (kt + 1) * 32, K, tid);
        uint32_t st = sb + (kt & 1) * STAGE_B;
        #pragma unroll
        for (int ks = 0; ks < 2; ++ks) {
            uint32_t ahi[2][4], alo[2][4], bhi[4][4], blo[4][4];
            #pragma unroll
            for (int mf = 0; mf < 2; ++mf)
                ldsm4(ahi[mf], st + (wm*32 + mf*16 + a_ro)*80 + (ks*16 + a_ko)*2);
            #pragma unroll
            for (int np = 0; np < 4; ++np)
                ldsm4(bhi[np], st + 2*ATILE_B + (wn*64 + np*16 + b_rp)*80 + (ks*16 + b_ko)*2);
            #pragma unroll
            for (int np = 0; np < 4; ++np)
                #pragma unroll
                for (int mf = 0; mf < 2; ++mf) {
                    mma16816(acc[mf][np*2  ], ahi[mf], &bhi[np][0]);
                    mma16816(acc[mf][np*2+1], ahi[mf], &bhi[np][2]);
                }
            #pragma unroll
            for (int np = 0; np < 4; ++np)
                ldsm4(blo[np], st + 2*ATILE_B + ATILE_B + (wn*64 + np*16 + b_rp)*80 + (ks*16 + b_ko)*2);
            #pragma unroll
            for (int np = 0; np < 4; ++np)
                #pragma unroll
                for (int mf = 0; mf < 2; ++mf) {
                    mma16816(acc[mf][np*2  ], ahi[mf], &blo[np][0]);
                    mma16816(acc[mf][np*2+1], ahi[mf], &blo[np][2]);
                }
            #pragma unroll
            for (int mf = 0; mf < 2; ++mf)
                ldsm4(alo[mf], st + ATILE_B + (wm*32 + mf*16 + a_ro)*80 + (ks*16 + a_ko)*2);
            #pragma unroll
            for (int np = 0; np < 4; ++np)
                #pragma unroll
                for (int mf = 0; mf < 2; ++mf) {
                    mma16816(acc[mf][np*2  ], alo[mf], &bhi[np][0]);
                    mma16816(acc[mf][np*2+1], alo[mf], &bhi[np][2]);
                }
        }
    }

    const int tr = lane >> 2;
    const int tc = (lane & 3) * 2;
    #pragma unroll
    for (int mf = 0; mf < 2; ++mf) {
        #pragma unroll
        for (int nf = 0; nf < 8; ++nf) {
            int gj = bn + wn*64 + nf*8 + tc;
            float2 b2 = *(const float2*)&bias[gj];
            #pragma unroll
            for (int h = 0; h < 2; ++h) {
                int gi = bm + wm*32 + mf*16 + tr + h*8;
                float v0 = acc[mf][nf][h*2]   + b2.x;
                float v1 = acc[mf][nf][h*2+1] + b2.y;
                size_t off = (size_t)gi * N + gj;
                if (EPI == 0) {
                    int wh = gj >> 10, hh = (gj >> 6) & 15, d = gj & 63;
                    int bb = gi >> 10, nn = gi & 1023;
                    size_t idx = (((size_t)(bb*16 + hh))*1024 + nn)*64 + d;
                    if (wh == 2) {
                        float2 o; o.x = v0; o.y = v1;
                        *(float2*)&g_v[idx] = o;
                    } else {
                        bf16 h0,l0,h1,l1;
                        bfsplit(v0,h0,l0); bfsplit(v1,h1,l1);
                        bf162 ph, pl; ph.x=h0; ph.y=h1; pl.x=l0; pl.y=l1;
                        if (wh == 0) { *(bf162*)&g_qh[idx]=ph; *(bf162*)&g_ql[idx]=pl; }
                        else         { *(bf162*)&g_kh[idx]=ph; *(bf162*)&g_kl[idx]=pl; }
                    }
                } else if (EPI == 1) {
                    float2 rr = *(const float2*)&res[off];
                    float2 o; o.x = v0 + rr.x; o.y = v1 + rr.y;
                    *(float2*)&outf[off] = o;
                } else if (EPI == 2) {
                    float2 m = *(const float2*)&aux[off];
                    v0 = (m.x > 0.5f) ? fmaxf(v0, 0.f) : 0.f;
                    v1 = (m.y > 0.5f) ? fmaxf(v1, 0.f) : 0.f;
                    bf16 h0,l0,h1,l1;
                    bfsplit(v0,h0,l0); bfsplit(v1,h1,l1);
                    bf162 p; p.x=h0; p.y=h1; *(bf162*)&outh[off] = p;
                    p.x=l0; p.y=l1;          *(bf162*)&outl[off] = p;
                } else {
                    float2 m  = *(const float2*)&aux[off];
                    float2 rr = *(const float2*)&res[off];
                    float2 o;
                    o.x = rr.x + ((m.x > 0.5f) ? v0 : 0.f);
                    o.y = rr.y + ((m.y > 0.5f) ? v1 : 0.f);
                    *(float2*)&outf[off] = o;
                }
            }
        }
    }
}

// ------- sparse attention: HMMA scores, early-exit top-k, compacted PV -----
#define SS_STR  1034
#define SS_OFF  20736
#define ATTN_SMEM (9216 + 73728 + 32*SS_STR*4)

__device__ __forceinline__ void issue_k(uint32_t sb, size_t bhoff, int kt, int buf, int tid) {
    #pragma unroll
    for (int i = 0; i < 4; ++i) {
        int lin = tid + (i << 9);
        int tile = lin >> 10, wit = lin & 1023;
        int r = wit >> 3, ch = wit & 7;
        const bf16* gsrc = (tile ? g_kl : g_kh) + bhoff + (size_t)(kt*128 + r)*64 + ch*8;
        CP_ASYNC16(sb + 9216 + buf*36864 + tile*18432 + r*144 + ch*16, gsrc);
    }
    CP_COMMIT();
}

__global__ void __launch_bounds__(512)
attn_kernel()
{
    extern __shared__ char smraw[];
    float* smf = (float*)smraw;
    uint32_t sb = s2u(smraw);

    int blk = blockIdx.x, bh = blk >> 5, n0 = (blk & 31) << 5;
    int tid = threadIdx.x, lane = tid & 31, w = tid >> 5;
    const size_t bhoff = (size_t)bh * 65536;

    {
        int tile = tid >> 8, wit = tid & 255, r = wit >> 3, ch = wit & 7;
        const bf16* gsrc = (tile ? g_ql : g_qh) + bhoff + (size_t)(n0 + r)*64 + ch*8;
        *(uint4*)(smraw + tile*4608 + r*144 + ch*16) = *(const uint4*)gsrc;
    }
    issue_k(sb, bhoff, 0, 0, tid);
    __syncthreads();

    const int wm = w & 1, wn = w >> 1;
    const int a_ro = lane & 15, a_ko = (lane >> 4) * 8;
    const int b_rp = ((lane >> 4) & 1) * 8 + (lane & 7);
    const int b_ko = ((lane >> 3) & 1) * 8;
    uint32_t qhi[4][4], qlo[4][4];
    #pragma unroll
    for (int ks = 0; ks < 4; ++ks) {
        uint32_t qa = sb + (wm*16 + a_ro)*144 + (ks*16 + a_ko)*2;
        ldsm4(qhi[ks], qa);
        ldsm4(qlo[ks], qa + 4608);
    }
    const int tr = lane >> 2, tc = (lane & 3) * 2;

    // ---- phase 1: scores via HMMA (double-buffered K) ----
    for (int kt = 0; kt < 8; ++kt) {
        CP_WAIT0();
        __syncthreads();
        if (kt < 7) issue_k(sb, bhoff, kt + 1, (kt + 1) & 1, tid);
        uint32_t kb = sb + 9216 + (kt & 1)*36864;
        float acc[2][4];
        #pragma unroll
        for (int nf = 0; nf < 2; ++nf)
            #pragma unroll
            for (int q = 0; q < 4; ++q) acc[nf][q] = 0.f;
        #pragma unroll
        for (int ks = 0; ks < 4; ++ks) {
            uint32_t bd = kb + (wn*16 + b_rp)*144 + (ks*16 + b_ko)*2;
            uint32_t bhi[4], blo[4];
            ldsm4(bhi, bd);
            ldsm4(blo, bd + 18432);
            mma16816(acc[0], qhi[ks], &bhi[0]);
            mma16816(acc[1], qhi[ks], &bhi[2]);
            mma16816(acc[0], qhi[ks], &blo[0]);
            mma16816(acc[1], qhi[ks], &blo[2]);
            mma16816(acc[0], qlo[ks], &bhi[0]);
            mma16816(acc[1], qlo[ks], &bhi[2]);
        }
        #pragma unroll
        for (int nf = 0; nf < 2; ++nf) {
            int key = kt*128 + wn*16 + nf*8 + tc;
            int row0 = wm*16 + tr;
            float2 o;
            o.x = acc[nf][0]*0.125f; o.y = acc[nf][1]*0.125f;
            *(float2*)&smf[SS_OFF + row0*SS_STR + key] = o;
            o.x = acc[nf][2]*0.125f; o.y = acc[nf][3]*0.125f;
            *(float2*)&smf[SS_OFF + (row0+8)*SS_STR + key] = o;
        }
    }
    __syncthreads();

    // ---- per-row: early-exit top-k threshold, softmax, compaction, PV ----
    int r0 = 2 * w;
    float o00=0, o01=0, o10=0, o11=0;
    const float* Vb = g_v + bhoff;
    #pragma unroll 1
    for (int rr = 0; rr < 2; ++rr) {
        float* srow = &smf[SS_OFF + (r0 + rr) * SS_STR];
        unsigned key[32];
        float lmax = -3.4e38f;
        #pragma unroll
        for (int i = 0; i < 32; ++i) {
            float s = srow[lane + 32*i];
            lmax = fmaxf(lmax, s);
            unsigned ub = __float_as_uint(s);
            key[i] = ub ^ (((unsigned)((int)ub >> 31)) | 0x80000000u);
        }
        #pragma unroll
        for (int o = 16; o; o >>= 1) lmax = fmaxf(lmax, __shfl_xor_sync(~0u, lmax, o));

        // binary search with exact-count early exit
        unsigned T;
        {
            unsigned lo = 0u, hi = 0xFFFFFFFFu;
            while (lo < hi) {
                unsigned mid = lo + (unsigned)(((unsigned long long)(hi - lo) + 1ull) >> 1);
                unsigned c = 0;
                #pragma unroll
                for (int i = 0; i < 32; ++i) c += (key[i] >= mid) ? 1u : 0u;
                c = __reduce_add_sync(~0u, c);
                if (c == (unsigned)KSP) { lo = mid; break; }
                if (c > (unsigned)KSP) lo = mid; else hi = mid - 1u;
            }
            T = lo;
        }

        // softmax denominator over selected
        float lsum = 0.f;
        #pragma unroll
        for (int i = 0; i < 32; ++i) {
            if (key[i] >= T) {
                unsigned ub = key[i];
                unsigned fb = ub ^ ((ub & 0x80000000u) ? 0x80000000u : 0xFFFFFFFFu);
                lsum += __expf(__uint_as_float(fb) - lmax);
            }
        }
        #pragma unroll
        for (int o = 16; o; o >>= 1) lsum += __shfl_xor_sync(~0u, lsum, o);
        float inv = 1.f / lsum;

        // compact (prob, pos) into the head of this row's smem (row consumed)
        uint2* lst = (uint2*)srow;
        int cnt = 0;
        #pragma unroll
        for (int i = 0; i < 32; ++i) {
            bool sel = key[i] >= T;
            unsigned mask = __ballot_sync(~0u, sel);
            if (sel) {
                int ofs = cnt + __popc(mask & ((1u << lane) - 1u));
                unsigned ub = key[i];
                unsigned fb = ub ^ ((ub & 0x80000000u) ? 0x80000000u : 0xFFFFFFFFu);
                float p = __expf(__uint_as_float(fb) - lmax) * inv;
                if (ofs < 128) {
                    uint2 e; e.x = __float_as_uint(p); e.y = (unsigned)(lane + 32*i);
                    lst[ofs] = e;
                }
            }
            cnt += __popc(mask);
        }
        if (cnt > 128) cnt = 128;
        __syncwarp();

        // sparse PV: direct coalesced LDG of selected V rows (L2-resident)
        float a0 = 0.f, a1 = 0.f;
        #pragma unroll 4
        for (int j = 0; j < cnt; ++j) {
            uint2 e = lst[j];
            float p = __uint_as_float(e.x);
            const float* vr = Vb + (size_t)e.y * 64;
            a0 = fmaf(p, __ldg(vr + lane),      a0);
            a1 = fmaf(p, __ldg(vr + lane + 32), a1);
        }
        if (rr == 0) { o00 = a0; o01 = a1; } else { o10 = a0; o11 = a1; }
    }

    int bb = bh >> 4, hh = bh & 15;
    #pragma unroll
    for (int rr = 0; rr < 2; ++rr) {
        size_t base = ((size_t)(bb*1024 + n0 + r0 + rr)) * 1024 + hh*64;
        bf16 h, l;
        bfsplit(rr ? o10 : o00, h, l);
        g_ath[base + lane] = h; g_atl[base + lane] = l;
        bfsplit(rr ? o11 : o01, h, l);
        g_ath[base + lane + 32] = h; g_atl[base + lane + 32] = l;
    }
}

// ---------------- launch ----------------
extern "C" void kernel_launch(void* const* d_in, const int* in_sizes, int n_in,
                              void* d_out, int out_size)
{
    (void)in_sizes; (void)n_in; (void)out_size;
    const float* x     = (const float*)d_in[0];
    const float* ln1_w = (const float*)d_in[1];
    const float* ln1_b = (const float*)d_in[2];
    const float* qkv_w = (const float*)d_in[3];
    const float* qkv_b = (const float*)d_in[4];
    const float* out_w = (const float*)d_in[5];
    const float* out_b = (const float*)d_in[6];
    const float* ln2_w = (const float*)d_in[7];
    const float* ln2_b = (const float*)d_in[8];
    const float* w1    = (const float*)d_in[9];
    const float* b1    = (const float*)d_in[10];
    const float* w2    = (const float*)d_in[11];
    const float* b2    = (const float*)d_in[12];
    const float* mask1 = (const float*)d_in[13];
    const float* mask2 = (const float*)d_in[14];
    float* out = (float*)d_out;

    void *x1, *xnh, *xnl, *hnh, *hnl, *ath, *atl, *h1h, *h1l,
         *qwh, *qwl, *owh, *owl, *w1h, *w1l, *w2h, *w2l;
    cudaGetSymbolAddress(&x1, g_x1);
    cudaGetSymbolAddress(&xnh, g_xnh); cudaGetSymbolAddress(&xnl, g_xnl);
    cudaGetSymbolAddress(&hnh, g_hnh); cudaGetSymbolAddress(&hnl, g_hnl);
    cudaGetSymbolAddress(&ath, g_ath); cudaGetSymbolAddress(&atl, g_atl);
    cudaGetSymbolAddress(&h1h, g_h1h); cudaGetSymbolAddress(&h1l, g_h1l);
    cudaGetSymbolAddress(&qwh, g_qwh); cudaGetSymbolAddress(&qwl, g_qwl);
    cudaGetSymbolAddress(&owh, g_owh); cudaGetSymbolAddress(&owl, g_owl);
    cudaGetSymbolAddress(&w1h, g_w1h); cudaGetSymbolAddress(&w1l, g_w1l);
    cudaGetSymbolAddress(&w2h, g_w2h); cudaGetSymbolAddress(&w2l, g_w2l);

    cudaFuncSetAttribute(attn_kernel, cudaFuncAttributeMaxDynamicSharedMemorySize, ATTN_SMEM);
    cudaFuncSetAttribute(tc_gemm<0>, cudaFuncAttributeMaxDynamicSharedMemorySize, GSMEM);
    cudaFuncSetAttribute(tc_gemm<1>, cudaFuncAttributeMaxDynamicSharedMemorySize, GSMEM);
    cudaFuncSetAttribute(tc_gemm<2>, cudaFuncAttributeMaxDynamicSharedMemorySize, GSMEM);
    cudaFuncSetAttribute(tc_gemm<3>, cudaFuncAttributeMaxDynamicSharedMemorySize, GSMEM);

    // launch order: [0]cvt4 [1]ln1 [2]gemm0 [3]attn  -> ncu captures attn
    cvt4<<<12288, 256>>>(qkv_w, (bf16*)qwh, (bf16*)qwl, 786432,
                         out_w, (bf16*)owh, (bf16*)owl, 262144,
                         w1,    (bf16*)w1h, (bf16*)w1l, 1048576,
                         w2,    (bf16*)w2h, (bf16*)w2l, 1048576);

    ln_bf16<<<M_, 256>>>(x, ln1_w, ln1_b, (bf16*)xnh, (bf16*)xnl);

    tc_gemm<0><<<dim3(24, 64), 256, GSMEM>>>((bf16*)xnh, (bf16*)xnl,
        (bf16*)qwh, (bf16*)qwl, qkv_b, nullptr, nullptr, nullptr, nullptr, nullptr,
        3*C_, C_);

    attn_kernel<<<BH_*(N_/32), 512, ATTN_SMEM>>>();

    tc_gemm<1><<<dim3(8, 64), 256, GSMEM>>>((bf16*)ath, (bf16*)atl,
        (bf16*)owh, (bf16*)owl, out_b, nullptr, x, (float*)x1, nullptr, nullptr,
        C_, C_);

    ln_bf16<<<M_, 256>>>((float*)x1, ln2_w, ln2_b, (bf16*)hnh, (bf16*)hnl);

    tc_gemm<2><<<dim3(32, 64), 256, GSMEM>>>((bf16*)hnh, (bf16*)hnl,
        (bf16*)w1h, (bf16*)w1l, b1, mask1, nullptr, nullptr, (bf16*)h1h, (bf16*)h1l,
        FF_, C_);

    tc_gemm<3><<<dim3(8, 64), 256, GSMEM>>>((bf16*)h1h, (bf16*)h1l,
        (bf16*)w2h, (bf16*)w2l, b2, mask2, (float*)x1, out, nullptr, nullptr,
        C_, FF_);
}